// round 1
// baseline (speedup 1.0000x reference)
#include <cuda_runtime.h>

#define NN     100000
#define NE     3200000
#define BGR    64
#define DIM    16
#define NFP    33
#define EMBD   128
#define LG     3000
#define LL     2998
#define NFILT  32
#define FCIN   3872    // 32*121
#define TMAX   65

// ---------------- device scratch (static, no allocation) ----------------
__device__ int    g_off[NN + 1];
__device__ int    g_cur[NN];
__device__ int    g_csr_src[NE];
__device__ float  g_csr_w[NE];
__device__ float  g_xbuf0[NN * DIM];
__device__ float  g_xbuf1[NN * DIM];
__device__ double g_stats[32];        // [0:16) sum, [16:32) sumsq
__device__ float  g_affine[32];       // [0:16) scale a, [16:32) shift b
__device__ float  g_pool[BGR * DIM];
__device__ int    g_bsum[128];
__device__ int    g_bpref[128];
__device__ float  g_wt[BGR * NFILT * TMAX * 8];
__device__ float  g_y[BGR * FCIN];

// ---------------- init ----------------
__global__ void k_init() {
    int i  = blockIdx.x * blockDim.x + threadIdx.x;
    int st = gridDim.x * blockDim.x;
    for (int j = i; j <= NN; j += st) g_off[j] = 0;
    if (i < 32) g_stats[i] = 0.0;
    for (int j = i; j < BGR * DIM; j += st) g_pool[j] = 0.f;
}

// ---------------- CSR build ----------------
__global__ void k_hist(const int* __restrict__ ei) {
    int i  = blockIdx.x * blockDim.x + threadIdx.x;
    int st = gridDim.x * blockDim.x;
    for (int e = i; e < NE; e += st) {
        int dst = ei[NE + e];
        atomicAdd(&g_off[dst + 1], 1);
    }
}

__global__ void k_scan1() {
    __shared__ int s[1024];
    int i = blockIdx.x * 1024 + threadIdx.x;
    int v = (i <= NN) ? g_off[i] : 0;
    s[threadIdx.x] = v;
    __syncthreads();
    for (int ofs = 1; ofs < 1024; ofs <<= 1) {
        int add = (threadIdx.x >= ofs) ? s[threadIdx.x - ofs] : 0;
        __syncthreads();
        s[threadIdx.x] += add;
        __syncthreads();
    }
    if (i <= NN) g_off[i] = s[threadIdx.x];
    if (threadIdx.x == 1023) g_bsum[blockIdx.x] = s[1023];
}

__global__ void k_scan2(int nb) {
    if (threadIdx.x == 0) {
        int acc = 0;
        for (int b = 0; b < nb; b++) { g_bpref[b] = acc; acc += g_bsum[b]; }
    }
}

__global__ void k_scan3() {
    int i = blockIdx.x * 1024 + threadIdx.x;
    if (i <= NN) {
        int v = g_off[i] + g_bpref[blockIdx.x];
        g_off[i] = v;
        if (i < NN) g_cur[i] = v;
    }
}

__global__ void k_scatter(const int* __restrict__ ei, const float* __restrict__ pw) {
    int i  = blockIdx.x * blockDim.x + threadIdx.x;
    int st = gridDim.x * blockDim.x;
    for (int e = i; e < NE; e += st) {
        int src = ei[e];
        int dst = ei[NE + e];
        int p   = atomicAdd(&g_cur[dst], 1);
        g_csr_src[p] = src;
        g_csr_w[p]   = pw[e];
    }
}

// ---------------- GINE layer 1 (33 -> 16), writes raw (pre-BN) y ----------------
__global__ void k_gine33(const float* __restrict__ px,
                         const float* __restrict__ W1, const float* __restrict__ b1,
                         const float* __restrict__ W2, const float* __restrict__ b2,
                         const float* __restrict__ ew, const float* __restrict__ ebv,
                         const float* __restrict__ epsp) {
    __shared__ float sW1[NFP * 16], sW2[256], sb1[16], sb2[16], sc[NFP], se[NFP];
    __shared__ float ssum[16], ssq[16];
    int t = threadIdx.x;
    for (int i = t; i < NFP * 16; i += 256) sW1[i] = W1[i];
    for (int i = t; i < 256; i += 256) sW2[i] = W2[i];
    if (t < 16) { sb1[t] = b1[t]; sb2[t] = b2[t]; ssum[t] = 0.f; ssq[t] = 0.f; }
    if (t < NFP) { sc[t] = ew[t]; se[t] = ebv[t]; }
    __syncthreads();
    float ope  = 1.f + epsp[0];
    int lane = t & 31;
    int gw   = blockIdx.x * 8 + (t >> 5);
    int nw   = gridDim.x * 8;
    float lsum = 0.f, lsq = 0.f;
    for (int n = gw; n < NN; n += nw) {
        int beg = g_off[n], end = g_off[n + 1];
        float acc = 0.f, acc32 = 0.f;
        for (int j = beg; j < end; j++) {
            int   src = g_csr_src[j];
            float w   = g_csr_w[j];
            float xv  = px[src * NFP + lane];
            acc += fmaxf(xv + w * sc[lane] + se[lane], 0.f);
            if (lane == 0) {
                float x2 = px[src * NFP + 32];
                acc32 += fmaxf(x2 + w * sc[32] + se[32], 0.f);
            }
        }
        float h   = ope * px[n * NFP + lane] + acc;
        float h32 = (lane == 0) ? (ope * px[n * NFP + 32] + acc32) : 0.f;
        float tj  = (lane < 16) ? sb1[lane] : 0.f;
        #pragma unroll
        for (int d = 0; d < 32; d++) {
            float hd = __shfl_sync(0xffffffffu, h, d);
            if (lane < 16) tj += hd * sW1[d * 16 + lane];
        }
        float h32b = __shfl_sync(0xffffffffu, h32, 0);
        if (lane < 16) tj += h32b * sW1[32 * 16 + lane];
        tj = fmaxf(tj, 0.f);
        float oj = (lane < 16) ? sb2[lane] : 0.f;
        #pragma unroll
        for (int d = 0; d < 16; d++) {
            float td = __shfl_sync(0xffffffffu, tj, d);
            if (lane < 16) oj += td * sW2[d * 16 + lane];
        }
        if (lane < 16) {
            float y = fmaxf(oj, 0.f);
            g_xbuf0[n * DIM + lane] = y;
            lsum += y; lsq += y * y;
        }
    }
    if (lane < 16) { atomicAdd(&ssum[lane], lsum); atomicAdd(&ssq[lane], lsq); }
    __syncthreads();
    if (t < 16) {
        atomicAdd(&g_stats[t],      (double)ssum[t]);
        atomicAdd(&g_stats[16 + t], (double)ssq[t]);
    }
}

// ---------------- BN finalize: affine coefs from stats, zero stats ----------------
__global__ void k_bnfinal(const float* __restrict__ gamma, const float* __restrict__ beta) {
    int t = threadIdx.x;
    if (t < 16) {
        double s = g_stats[t], q = g_stats[16 + t];
        float mu  = (float)(s / (double)NN);
        float var = (float)(q / (double)NN) - mu * mu;
        float a   = gamma[t] * rsqrtf(fmaxf(var, 0.f) + 1e-5f);
        g_affine[t]      = a;
        g_affine[16 + t] = beta[t] - mu * a;
    }
    if (t < 32) g_stats[t] = 0.0;
}

// ---------------- GINE layers 2..5 (16 -> 16), input affine applied on the fly ----------------
__global__ void k_gine16(const float* __restrict__ W1, const float* __restrict__ b1,
                         const float* __restrict__ W2, const float* __restrict__ b2,
                         const float* __restrict__ ew, const float* __restrict__ ebv,
                         const float* __restrict__ epsp, int flip) {
    const float* xin  = flip ? g_xbuf1 : g_xbuf0;
    float*       xout = flip ? g_xbuf0 : g_xbuf1;
    __shared__ float sW1[256], sW2[256], sb1[16], sb2[16], sc[16], se[16], sa[16], sbb[16];
    __shared__ float ssum[16], ssq[16];
    int t = threadIdx.x;
    for (int i = t; i < 256; i += 256) { sW1[i] = W1[i]; sW2[i] = W2[i]; }
    if (t < 16) {
        sb1[t] = b1[t]; sb2[t] = b2[t]; sc[t] = ew[t]; se[t] = ebv[t];
        sa[t] = g_affine[t]; sbb[t] = g_affine[16 + t];
        ssum[t] = 0.f; ssq[t] = 0.f;
    }
    __syncthreads();
    float ope  = 1.f + epsp[0];
    int lane = t & 31;
    int d    = lane & 15;
    int half = lane >> 4;
    int gw   = blockIdx.x * 8 + (t >> 5);
    int nw   = gridDim.x * 8;
    float lsum = 0.f, lsq = 0.f;
    for (int n = gw; n < NN; n += nw) {
        int beg = g_off[n], end = g_off[n + 1];
        float acc = 0.f;
        for (int j = beg + half; j < end; j += 2) {
            int   src = g_csr_src[j];
            float w   = g_csr_w[j];
            float xv  = fmaf(sa[d], xin[src * DIM + d], sbb[d]);
            acc += fmaxf(xv + w * sc[d] + se[d], 0.f);
        }
        acc += __shfl_down_sync(0xffffffffu, acc, 16);
        float h = 0.f;
        if (lane < 16) {
            float xn = fmaf(sa[lane], xin[n * DIM + lane], sbb[lane]);
            h = ope * xn + acc;
        }
        float tj = (lane < 16) ? sb1[lane] : 0.f;
        #pragma unroll
        for (int dd = 0; dd < 16; dd++) {
            float hd = __shfl_sync(0xffffffffu, h, dd);
            if (lane < 16) tj += hd * sW1[dd * 16 + lane];
        }
        tj = fmaxf(tj, 0.f);
        float oj = (lane < 16) ? sb2[lane] : 0.f;
        #pragma unroll
        for (int dd = 0; dd < 16; dd++) {
            float td = __shfl_sync(0xffffffffu, tj, dd);
            if (lane < 16) oj += td * sW2[dd * 16 + lane];
        }
        if (lane < 16) {
            float y = fmaxf(oj, 0.f);
            xout[n * DIM + lane] = y;
            lsum += y; lsq += y * y;
        }
    }
    if (lane < 16) { atomicAdd(&ssum[lane], lsum); atomicAdd(&ssq[lane], lsq); }
    __syncthreads();
    if (t < 16) {
        atomicAdd(&g_stats[t],      (double)ssum[t]);
        atomicAdd(&g_stats[16 + t], (double)ssq[t]);
    }
}

// ---------------- global mean pool (sums only; counts via binary search in head) ----------------
__global__ void k_pool(const int* __restrict__ batch) {
    __shared__ float sp[BGR * DIM];
    __shared__ float sa[16], sbb[16];
    int t = threadIdx.x;
    for (int i = t; i < BGR * DIM; i += 256) sp[i] = 0.f;
    if (t < 16) { sa[t] = g_affine[t]; sbb[t] = g_affine[16 + t]; }
    __syncthreads();
    int st = gridDim.x * 256;
    for (int idx = blockIdx.x * 256 + t; idx < NN * DIM; idx += st) {
        int n = idx >> 4, dd = idx & 15;
        int bt = batch[n];
        float v = fmaf(sa[dd], g_xbuf0[idx], sbb[dd]);
        atomicAdd(&sp[bt * DIM + dd], v);
    }
    __syncthreads();
    for (int i = t; i < BGR * DIM; i += 256) atomicAdd(&g_pool[i], sp[i]);
}

__device__ __forceinline__ int lbound(const int* a, int n, int key) {
    int lo = 0, hi = n;
    while (lo < hi) { int mid = (lo + hi) >> 1; if (a[mid] < key) lo = mid + 1; else hi = mid; }
    return lo;
}

__global__ void k_head(const int* __restrict__ batch,
                       const float* __restrict__ fw, const float* __restrict__ fb,
                       float* __restrict__ out) {
    __shared__ float sm[16];
    __shared__ int scnt;
    int b = blockIdx.x, t = threadIdx.x;
    if (t == 0) {
        int lo = lbound(batch, NN, b);
        int hi = lbound(batch, NN, b + 1);
        scnt = max(hi - lo, 1);
    }
    __syncthreads();
    if (t < 16) sm[t] = g_pool[b * DIM + t] / (float)scnt;
    __syncthreads();
    float acc = fb[t];
    #pragma unroll
    for (int dd = 0; dd < 16; dd++) acc += sm[dd] * fw[dd * EMBD + t];
    out[BGR * EMBD + b * EMBD + t] = fmaxf(acc, 0.f);
}

// ---------------- RNA: bucketized conv weights W~[b,f,t,k] ----------------
__global__ void k_wtilde(const int* __restrict__ tok, const float* __restrict__ w,
                         int L, int T) {
    __shared__ float s[TMAX * 8];
    int bf = blockIdx.x;
    int b = bf >> 5, f = bf & 31;
    int t = threadIdx.x;
    for (int i = t; i < T * 8; i += 256) s[i] = 0.f;
    __syncthreads();
    const int*   tb = tok + b * L;
    const float* wf = w + (size_t)f * L * 8;
    for (int c = t; c < L; c += 256) {
        int tv = tb[c];
        const float* wc = wf + c * 8;
        #pragma unroll
        for (int k = 0; k < 8; k++) atomicAdd(&s[tv * 8 + k], wc[k]);
    }
    __syncthreads();
    float* o = g_wt + (size_t)bf * (TMAX * 8);
    for (int i = t; i < T * 8; i += 256) o[i] = s[i];
}

// ---------------- RNA: y[b,f,h] = cb[f] + sum_{t,k} W~ * emb[t,h+k] ----------------
__global__ void k_convy(const float* __restrict__ emb, const float* __restrict__ cb, int T) {
    __shared__ float swt[TMAX * 8];
    int bf = blockIdx.x;
    int b = bf >> 5, f = bf & 31;
    int t = threadIdx.x;  // h
    const float* src = g_wt + (size_t)bf * (TMAX * 8);
    for (int i = t; i < T * 8; i += 128) swt[i] = src[i];
    __syncthreads();
    if (t < 121) {
        float acc = cb[f];
        for (int tt = 0; tt < T; tt++) {
            const float* er = emb + tt * EMBD;
            #pragma unroll
            for (int k = 0; k < 8; k++) acc += swt[tt * 8 + k] * er[t + k];
        }
        g_y[b * FCIN + f * 121 + t] = acc;
    }
}

// ---------------- RNA: fc_xr + 0.5*(xrg+xrl) fold into out ----------------
__global__ void k_fc(const float* __restrict__ fw, const float* __restrict__ fb,
                     float* __restrict__ out, int mode) {
    __shared__ float sy[FCIN];
    int b = blockIdx.x, t = threadIdx.x;
    for (int i = t; i < FCIN; i += 128) sy[i] = g_y[b * FCIN + i];
    __syncthreads();
    float acc = fb[t];
    #pragma unroll 4
    for (int i = 0; i < FCIN; i++) acc += sy[i] * fw[i * EMBD + t];
    float* o = &out[b * EMBD + t];
    if (mode == 0) *o = 0.5f * acc;
    else           *o += 0.5f * acc;
}

// ---------------- launch ----------------
extern "C" void kernel_launch(void* const* d_in, const int* in_sizes, int n_in,
                              void* d_out, int out_size) {
    const float* px   = (const float*)d_in[0];
    const int*   ei   = (const int*)d_in[1];
    const float* pw   = (const float*)d_in[2];
    const int*   pbat = (const int*)d_in[3];
    const int*   rg   = (const int*)d_in[4];
    const int*   rl   = (const int*)d_in[5];
    const float* g1w1 = (const float*)d_in[6];
    const float* g1b1 = (const float*)d_in[7];
    const float* g1w2 = (const float*)d_in[8];
    const float* g1b2 = (const float*)d_in[9];
    const float* g1ew = (const float*)d_in[10];
    const float* g1eb = (const float*)d_in[11];
    const float* g1ep = (const float*)d_in[12];
    const float* gw1  = (const float*)d_in[13];
    const float* gb1  = (const float*)d_in[14];
    const float* gw2  = (const float*)d_in[15];
    const float* gb2  = (const float*)d_in[16];
    const float* gew  = (const float*)d_in[17];
    const float* geb  = (const float*)d_in[18];
    const float* gep  = (const float*)d_in[19];
    const float* bng  = (const float*)d_in[20];
    const float* bnb  = (const float*)d_in[21];
    const float* fxpw = (const float*)d_in[22];
    const float* fxpb = (const float*)d_in[23];
    const float* emb1 = (const float*)d_in[24];
    const float* emb2 = (const float*)d_in[25];
    const float* c1w  = (const float*)d_in[26];
    const float* c1b  = (const float*)d_in[27];
    const float* c2w  = (const float*)d_in[28];
    const float* c2b  = (const float*)d_in[29];
    const float* fxw  = (const float*)d_in[30];
    const float* fxb  = (const float*)d_in[31];
    float* out = (float*)d_out;

    const int NB_SCAN = (NN + 1 + 1023) / 1024;  // 98

    k_init<<<128, 256>>>();
    k_hist<<<1024, 256>>>(ei);
    k_scan1<<<NB_SCAN, 1024>>>();
    k_scan2<<<1, 32>>>(NB_SCAN);
    k_scan3<<<NB_SCAN, 1024>>>();
    k_scatter<<<1024, 256>>>(ei, pw);

    // RNA branches (independent; interleave for overlap potential later)
    k_wtilde<<<BGR * NFILT, 256>>>(rg, c1w, LG, 5);
    k_convy<<<BGR * NFILT, 128>>>(emb1, c1b, 5);
    k_fc<<<BGR, 128>>>(fxw, fxb, out, 0);
    k_wtilde<<<BGR * NFILT, 256>>>(rl, c2w, LL, 65);
    k_convy<<<BGR * NFILT, 128>>>(emb2, c2b, 65);
    k_fc<<<BGR, 128>>>(fxw, fxb, out, 1);

    // Protein GINE stack
    k_gine33<<<1184, 256>>>(px, g1w1, g1b1, g1w2, g1b2, g1ew, g1eb, g1ep);
    k_bnfinal<<<1, 32>>>(bng, bnb);
    for (int i = 0; i < 4; i++) {
        k_gine16<<<1184, 256>>>(gw1 + i * 256, gb1 + i * 16,
                                gw2 + i * 256, gb2 + i * 16,
                                gew + i * 16,  geb + i * 16,
                                gep + i, i & 1);
        k_bnfinal<<<1, 32>>>(bng + (i + 1) * 16, bnb + (i + 1) * 16);
    }
    k_pool<<<296, 256>>>(pbat);
    k_head<<<BGR, 128>>>(pbat, fxpw, fxpb, out);
}

// round 2
// speedup vs baseline: 2.2502x; 2.2502x over previous
#include <cuda_runtime.h>

#define NN     100000
#define NE     3200000
#define BGR    64
#define DIM    16
#define NFP    33
#define EMBD   128
#define LG     3000
#define LL     2998
#define NFILT  32
#define FCIN   3872    // 32*121
#define TMAX   65
#define FULL   0xffffffffu

// ---------------- device scratch (static, no allocation) ----------------
__device__ int    g_off[NN + 1];
__device__ int    g_cur[NN];
__device__ int    g_csr_src[NE];
__device__ float  g_csr_w[NE];
__device__ float4 g_xb0[NN * 4];       // 16 floats per node
__device__ float4 g_xb1[NN * 4];
__device__ float4 g_pxp[NN * 9];       // padded 36-dim copy of pro_x
__device__ double g_stats[32];         // [0:16) sum, [16:32) sumsq
__device__ float  g_affine[32];        // [0:16) scale a, [16:32) shift b
__device__ float  g_pool[BGR * DIM];
__device__ int    g_bsum[128];
__device__ int    g_bpref[128];
__device__ int    g_boffG[BGR * (TMAX + 1)];
__device__ int    g_boffL[BGR * (TMAX + 1)];
__device__ int    g_blistG[BGR * LG];
__device__ int    g_blistL[BGR * LL];
__device__ float  g_wtG[BGR * NFILT * 5 * 8];
__device__ float  g_wtL[BGR * NFILT * TMAX * 8];
__device__ float  g_yG[BGR * FCIN];
__device__ float  g_yL[BGR * FCIN];

// ---------------- init ----------------
__global__ void k_init() {
    int i  = blockIdx.x * blockDim.x + threadIdx.x;
    int st = gridDim.x * blockDim.x;
    for (int j = i; j <= NN; j += st) g_off[j] = 0;
    if (i < 32) g_stats[i] = 0.0;
    for (int j = i; j < BGR * DIM; j += st) g_pool[j] = 0.f;
}

// ---------------- pad pro_x to 36 dims (float4-aligned rows) ----------------
__global__ void k_pad(const float* __restrict__ px) {
    int i  = blockIdx.x * blockDim.x + threadIdx.x;
    int st = gridDim.x * blockDim.x;
    float* o = (float*)g_pxp;
    for (int idx = i; idx < NN * 36; idx += st) {
        int n = idx / 36, d = idx - n * 36;
        o[idx] = (d < NFP) ? px[n * NFP + d] : 0.f;
    }
}

// ---------------- CSR build ----------------
__global__ void k_hist(const int* __restrict__ ei) {
    int i  = blockIdx.x * blockDim.x + threadIdx.x;
    int st = gridDim.x * blockDim.x;
    for (int e = i; e < NE; e += st) atomicAdd(&g_off[ei[NE + e] + 1], 1);
}

__global__ void k_scan1() {
    __shared__ int s[1024];
    int i = blockIdx.x * 1024 + threadIdx.x;
    int v = (i <= NN) ? g_off[i] : 0;
    s[threadIdx.x] = v;
    __syncthreads();
    for (int ofs = 1; ofs < 1024; ofs <<= 1) {
        int add = (threadIdx.x >= ofs) ? s[threadIdx.x - ofs] : 0;
        __syncthreads();
        s[threadIdx.x] += add;
        __syncthreads();
    }
    if (i <= NN) g_off[i] = s[threadIdx.x];
    if (threadIdx.x == 1023) g_bsum[blockIdx.x] = s[1023];
}

__global__ void k_scan2(int nb) {
    __shared__ int s[128];
    int t = threadIdx.x;
    int v = (t < nb) ? g_bsum[t] : 0;
    s[t] = v;
    __syncthreads();
    for (int ofs = 1; ofs < 128; ofs <<= 1) {
        int add = (t >= ofs) ? s[t - ofs] : 0;
        __syncthreads();
        s[t] += add;
        __syncthreads();
    }
    if (t < nb) g_bpref[t] = s[t] - v;   // exclusive
}

__global__ void k_scan3() {
    int i = blockIdx.x * 1024 + threadIdx.x;
    if (i <= NN) {
        int v = g_off[i] + g_bpref[blockIdx.x];
        g_off[i] = v;
        if (i < NN) g_cur[i] = v;
    }
}

__global__ void k_scatter(const int* __restrict__ ei, const float* __restrict__ pw) {
    int i  = blockIdx.x * blockDim.x + threadIdx.x;
    int st = gridDim.x * blockDim.x;
    for (int e = i; e < NE; e += st) {
        int src = ei[e];
        int dst = ei[NE + e];
        int p   = atomicAdd(&g_cur[dst], 1);
        g_csr_src[p] = src;
        g_csr_w[p]   = pw[e];
    }
}

// ---------------- GINE layer 1 (33 -> 16): 8 edges in flight per warp ----------------
__global__ void k_gine33(const float* __restrict__ W1, const float* __restrict__ b1,
                         const float* __restrict__ W2, const float* __restrict__ b2,
                         const float* __restrict__ ew, const float* __restrict__ ebv,
                         const float* __restrict__ epsp) {
    __shared__ float sW1[NFP * 16], sW2[256], sb1[16], sb2[16], sc[36], se[36];
    __shared__ float ssum[16], ssq[16];
    int t = threadIdx.x;
    for (int i = t; i < NFP * 16; i += 256) sW1[i] = W1[i];
    for (int i = t; i < 256; i += 256) sW2[i] = W2[i];
    if (t < 16) { sb1[t] = b1[t]; sb2[t] = b2[t]; ssum[t] = 0.f; ssq[t] = 0.f; }
    if (t < 36) { sc[t] = (t < NFP) ? ew[t] : 0.f; se[t] = (t < NFP) ? ebv[t] : 0.f; }
    __syncthreads();
    float ope = 1.f + epsp[0];
    int lane  = t & 31;
    int eslot = lane >> 2, q = lane & 3;
    // per-lane loop-invariant edge coefs
    float cA0 = sc[q*4+0], cA1 = sc[q*4+1], cA2 = sc[q*4+2], cA3 = sc[q*4+3];
    float eA0 = se[q*4+0], eA1 = se[q*4+1], eA2 = se[q*4+2], eA3 = se[q*4+3];
    float cB0 = sc[(q+4)*4+0], cB1 = sc[(q+4)*4+1], cB2 = sc[(q+4)*4+2], cB3 = sc[(q+4)*4+3];
    float eB0 = se[(q+4)*4+0], eB1 = se[(q+4)*4+1], eB2 = se[(q+4)*4+2], eB3 = se[(q+4)*4+3];
    float c32 = sc[32], e32 = se[32];
    int gw = blockIdx.x * 8 + (t >> 5);
    int nw = gridDim.x * 8;
    float lsum = 0.f, lsq = 0.f;
    for (int n = gw; n < NN; n += nw) {
        int beg = g_off[n], end = g_off[n + 1];
        float ax=0,ay=0,az=0,aw=0, bx=0,by=0,bz=0,bw=0, a32=0;
        for (int j = beg + eslot; j < end; j += 8) {
            int   src = __ldg(&g_csr_src[j]);
            float wv  = __ldg(&g_csr_w[j]);
            const float4* row = g_pxp + src * 9;
            float4 xa = row[q];
            float4 xb = row[q + 4];
            ax += fmaxf(xa.x + fmaf(wv, cA0, eA0), 0.f);
            ay += fmaxf(xa.y + fmaf(wv, cA1, eA1), 0.f);
            az += fmaxf(xa.z + fmaf(wv, cA2, eA2), 0.f);
            aw += fmaxf(xa.w + fmaf(wv, cA3, eA3), 0.f);
            bx += fmaxf(xb.x + fmaf(wv, cB0, eB0), 0.f);
            by += fmaxf(xb.y + fmaf(wv, cB1, eB1), 0.f);
            bz += fmaxf(xb.z + fmaf(wv, cB2, eB2), 0.f);
            bw += fmaxf(xb.w + fmaf(wv, cB3, eB3), 0.f);
            if (q == 0) {
                float x32 = ((const float*)row)[32];
                a32 += fmaxf(x32 + fmaf(wv, c32, e32), 0.f);
            }
        }
        #pragma unroll
        for (int ofs = 4; ofs < 32; ofs <<= 1) {
            ax += __shfl_xor_sync(FULL, ax, ofs); ay += __shfl_xor_sync(FULL, ay, ofs);
            az += __shfl_xor_sync(FULL, az, ofs); aw += __shfl_xor_sync(FULL, aw, ofs);
            bx += __shfl_xor_sync(FULL, bx, ofs); by += __shfl_xor_sync(FULL, by, ofs);
            bz += __shfl_xor_sync(FULL, bz, ofs); bw += __shfl_xor_sync(FULL, bw, ofs);
            a32 += __shfl_xor_sync(FULL, a32, ofs);
        }
        // redistribute: lane d holds agg for dim d (0..31)
        int srcl = (lane >> 2) & 3;
        float vax = __shfl_sync(FULL, ax, srcl), vay = __shfl_sync(FULL, ay, srcl);
        float vaz = __shfl_sync(FULL, az, srcl), vaw = __shfl_sync(FULL, aw, srcl);
        float vbx = __shfl_sync(FULL, bx, srcl), vby = __shfl_sync(FULL, by, srcl);
        float vbz = __shfl_sync(FULL, bz, srcl), vbw = __shfl_sync(FULL, bw, srcl);
        float gx = (lane >= 16) ? vbx : vax;
        float gy = (lane >= 16) ? vby : vay;
        float gz = (lane >= 16) ? vbz : vaz;
        float gwv = (lane >= 16) ? vbw : vaw;
        float lo = (lane & 1) ? gy : gx;
        float hi = (lane & 1) ? gwv : gz;
        float aggv = (lane & 2) ? hi : lo;
        float agg32 = __shfl_sync(FULL, a32, 0);
        const float* nrow = (const float*)(g_pxp + n * 9);
        float h   = ope * nrow[lane] + aggv;   // dims 0..31
        float h32 = ope * nrow[32] + agg32;
        float tj = (lane < 16) ? sb1[lane] : 0.f;
        #pragma unroll
        for (int d = 0; d < 32; d++) {
            float hd = __shfl_sync(FULL, h, d);
            if (lane < 16) tj = fmaf(hd, sW1[d * 16 + lane], tj);
        }
        if (lane < 16) tj = fmaf(h32, sW1[32 * 16 + lane], tj);
        tj = fmaxf(tj, 0.f);
        float oj = (lane < 16) ? sb2[lane] : 0.f;
        #pragma unroll
        for (int d = 0; d < 16; d++) {
            float td = __shfl_sync(FULL, tj, d);
            if (lane < 16) oj = fmaf(td, sW2[d * 16 + lane], oj);
        }
        if (lane < 16) {
            float y = fmaxf(oj, 0.f);
            ((float*)g_xb0)[n * DIM + lane] = y;
            lsum += y; lsq += y * y;
        }
    }
    if (lane < 16) { atomicAdd(&ssum[lane], lsum); atomicAdd(&ssq[lane], lsq); }
    __syncthreads();
    if (t < 16) {
        atomicAdd(&g_stats[t],      (double)ssum[t]);
        atomicAdd(&g_stats[16 + t], (double)ssq[t]);
    }
}

// ---------------- BN finalize ----------------
__global__ void k_bnfinal(const float* __restrict__ gamma, const float* __restrict__ beta) {
    int t = threadIdx.x;
    if (t < 16) {
        double s = g_stats[t], q = g_stats[16 + t];
        float mu  = (float)(s / (double)NN);
        float var = (float)(q / (double)NN) - mu * mu;
        float a   = gamma[t] * rsqrtf(fmaxf(var, 0.f) + 1e-5f);
        g_affine[t]      = a;
        g_affine[16 + t] = beta[t] - mu * a;
    }
    if (t < 32) g_stats[t] = 0.0;
}

// ---------------- GINE layers 2..5 (16 -> 16): 8 edges in flight per warp ----------------
__global__ void k_gine16(const float* __restrict__ W1, const float* __restrict__ b1,
                         const float* __restrict__ W2, const float* __restrict__ b2,
                         const float* __restrict__ ew, const float* __restrict__ ebv,
                         const float* __restrict__ epsp, int flip) {
    const float4* xin4 = flip ? g_xb1 : g_xb0;
    float*        xout = (float*)(flip ? g_xb0 : g_xb1);
    const float*  xin  = (const float*)xin4;
    __shared__ float sW1[256], sW2[256], sb1[16], sb2[16], sc[16], se[16], sa[16], sbb[16];
    __shared__ float ssum[16], ssq[16];
    int t = threadIdx.x;
    for (int i = t; i < 256; i += 256) { sW1[i] = W1[i]; sW2[i] = W2[i]; }
    if (t < 16) {
        sb1[t] = b1[t]; sb2[t] = b2[t]; sc[t] = ew[t]; se[t] = ebv[t];
        sa[t] = g_affine[t]; sbb[t] = g_affine[16 + t];
        ssum[t] = 0.f; ssq[t] = 0.f;
    }
    __syncthreads();
    float ope = 1.f + epsp[0];
    int lane  = t & 31;
    int eslot = lane >> 2, q = lane & 3;
    float a0 = sa[q*4+0], a1 = sa[q*4+1], a2 = sa[q*4+2], a3 = sa[q*4+3];
    float p0 = sbb[q*4+0], p1 = sbb[q*4+1], p2 = sbb[q*4+2], p3 = sbb[q*4+3];
    float c0 = sc[q*4+0], c1 = sc[q*4+1], c2 = sc[q*4+2], c3 = sc[q*4+3];
    float e0 = se[q*4+0], e1 = se[q*4+1], e2 = se[q*4+2], e3 = se[q*4+3];
    int gw = blockIdx.x * 8 + (t >> 5);
    int nw = gridDim.x * 8;
    float lsum = 0.f, lsq = 0.f;
    for (int n = gw; n < NN; n += nw) {
        int beg = g_off[n], end = g_off[n + 1];
        float ax = 0.f, ay = 0.f, az = 0.f, aw = 0.f;
        for (int j = beg + eslot; j < end; j += 8) {
            int   src = __ldg(&g_csr_src[j]);
            float wv  = __ldg(&g_csr_w[j]);
            float4 xv = xin4[src * 4 + q];
            ax += fmaxf(fmaf(a0, xv.x, p0) + fmaf(wv, c0, e0), 0.f);
            ay += fmaxf(fmaf(a1, xv.y, p1) + fmaf(wv, c1, e1), 0.f);
            az += fmaxf(fmaf(a2, xv.z, p2) + fmaf(wv, c2, e2), 0.f);
            aw += fmaxf(fmaf(a3, xv.w, p3) + fmaf(wv, c3, e3), 0.f);
        }
        #pragma unroll
        for (int ofs = 4; ofs < 32; ofs <<= 1) {
            ax += __shfl_xor_sync(FULL, ax, ofs); ay += __shfl_xor_sync(FULL, ay, ofs);
            az += __shfl_xor_sync(FULL, az, ofs); aw += __shfl_xor_sync(FULL, aw, ofs);
        }
        float vx = __shfl_sync(FULL, ax, lane >> 2);
        float vy = __shfl_sync(FULL, ay, lane >> 2);
        float vz = __shfl_sync(FULL, az, lane >> 2);
        float vw = __shfl_sync(FULL, aw, lane >> 2);
        float lo = (lane & 1) ? vy : vx;
        float hi = (lane & 1) ? vw : vz;
        float aggv = (lane & 2) ? hi : lo;
        float h = 0.f;
        if (lane < 16) {
            float xn = fmaf(sa[lane], xin[n * DIM + lane], sbb[lane]);
            h = ope * xn + aggv;
        }
        float tj = (lane < 16) ? sb1[lane] : 0.f;
        #pragma unroll
        for (int dd = 0; dd < 16; dd++) {
            float hd = __shfl_sync(FULL, h, dd);
            if (lane < 16) tj = fmaf(hd, sW1[dd * 16 + lane], tj);
        }
        tj = fmaxf(tj, 0.f);
        float oj = (lane < 16) ? sb2[lane] : 0.f;
        #pragma unroll
        for (int dd = 0; dd < 16; dd++) {
            float td = __shfl_sync(FULL, tj, dd);
            if (lane < 16) oj = fmaf(td, sW2[dd * 16 + lane], oj);
        }
        if (lane < 16) {
            float y = fmaxf(oj, 0.f);
            xout[n * DIM + lane] = y;
            lsum += y; lsq += y * y;
        }
    }
    if (lane < 16) { atomicAdd(&ssum[lane], lsum); atomicAdd(&ssq[lane], lsq); }
    __syncthreads();
    if (t < 16) {
        atomicAdd(&g_stats[t],      (double)ssum[t]);
        atomicAdd(&g_stats[16 + t], (double)ssq[t]);
    }
}

// ---------------- global mean pool ----------------
__global__ void k_pool(const int* __restrict__ batch) {
    __shared__ float sp[BGR * DIM];
    __shared__ float sa[16], sbb[16];
    int t = threadIdx.x;
    for (int i = t; i < BGR * DIM; i += 256) sp[i] = 0.f;
    if (t < 16) { sa[t] = g_affine[t]; sbb[t] = g_affine[16 + t]; }
    __syncthreads();
    int st = gridDim.x * 256;
    const float* xb = (const float*)g_xb0;
    for (int idx = blockIdx.x * 256 + t; idx < NN * DIM; idx += st) {
        int n = idx >> 4, dd = idx & 15;
        int bt = batch[n];
        float v = fmaf(sa[dd], xb[idx], sbb[dd]);
        atomicAdd(&sp[bt * DIM + dd], v);
    }
    __syncthreads();
    for (int i = t; i < BGR * DIM; i += 256) atomicAdd(&g_pool[i], sp[i]);
}

__device__ __forceinline__ int lbound(const int* a, int n, int key) {
    int lo = 0, hi = n;
    while (lo < hi) { int mid = (lo + hi) >> 1; if (a[mid] < key) lo = mid + 1; else hi = mid; }
    return lo;
}

__global__ void k_head(const int* __restrict__ batch,
                       const float* __restrict__ fw, const float* __restrict__ fb,
                       float* __restrict__ out) {
    __shared__ float sm[16];
    __shared__ int scnt;
    int b = blockIdx.x, t = threadIdx.x;
    if (t == 0) {
        int lo = lbound(batch, NN, b);
        int hi = lbound(batch, NN, b + 1);
        scnt = max(hi - lo, 1);
    }
    __syncthreads();
    if (t < 16) sm[t] = g_pool[b * DIM + t] / (float)scnt;
    __syncthreads();
    float acc = fb[t];
    #pragma unroll
    for (int dd = 0; dd < 16; dd++) acc += sm[dd] * fw[dd * EMBD + t];
    out[BGR * EMBD + b * EMBD + t] = fmaxf(acc, 0.f);
}

// ---------------- RNA: bucket build per batch row ----------------
__global__ void k_bucket(const int* __restrict__ tok, int L, int T,
                         int* __restrict__ list, int* __restrict__ boff) {
    __shared__ int cnt[TMAX + 1];
    __shared__ int offs[TMAX + 1];
    int b = blockIdx.x, t = threadIdx.x;
    if (t <= T) cnt[t] = 0;
    __syncthreads();
    const int* tb = tok + b * L;
    for (int c = t; c < L; c += 256) atomicAdd(&cnt[tb[c]], 1);
    __syncthreads();
    if (t == 0) {
        int acc = 0;
        for (int i = 0; i < T; i++) { offs[i] = acc; acc += cnt[i]; }
        offs[T] = acc;
    }
    __syncthreads();
    if (t <= T) boff[b * (TMAX + 1) + t] = offs[t];
    if (t < T) cnt[t] = offs[t];   // reuse as cursors
    __syncthreads();
    for (int c = t; c < L; c += 256) {
        int pos = atomicAdd(&cnt[tb[c]], 1);
        list[b * L + pos] = c;
    }
}

// ---------------- RNA: W~[b,f,t,k] = sum_{c in bucket t} w[f,c,k], no atomics ----------------
__global__ void k_wtilde2(const float* __restrict__ w,
                          const int* __restrict__ list, const int* __restrict__ boff,
                          int L, int T, int parts, float* __restrict__ wt) {
    __shared__ int soff[TMAX + 1];
    __shared__ float sred[256];
    int bf = blockIdx.x;
    int b = bf >> 5, f = bf & 31;
    int tid = threadIdx.x;
    if (tid <= T) soff[tid] = boff[b * (TMAX + 1) + tid];
    __syncthreads();
    int items = T * 8;
    const int*   lst = list + b * L;
    const float* wf  = w + (size_t)f * L * 8;
    float* o = wt + (size_t)bf * items;
    if (parts > 1) {
        int item = tid % items;
        int part = tid / items;
        float acc = 0.f;
        if (part < parts) {
            int tt = item >> 3, k = item & 7;
            int lo = soff[tt], hi = soff[tt + 1];
            for (int p = lo + part; p < hi; p += parts) {
                int c = lst[p];
                acc += wf[c * 8 + k];
            }
        }
        sred[tid] = acc;
        __syncthreads();
        if (tid < items) {
            float s = 0.f;
            for (int p = 0; p < parts; p++) s += sred[p * items + tid];
            o[tid] = s;
        }
    } else {
        for (int item = tid; item < items; item += 256) {
            int tt = item >> 3, k = item & 7;
            int lo = soff[tt], hi = soff[tt + 1];
            float acc = 0.f;
            for (int p = lo; p < hi; p++) {
                int c = lst[p];
                acc += wf[c * 8 + k];
            }
            o[item] = acc;
        }
    }
}

// ---------------- RNA: y[b,f,h] = cb[f] + sum_{t,k} W~ * emb[t,h+k] ----------------
__global__ void k_convy(const float* __restrict__ emb, const float* __restrict__ cb,
                        int T, const float* __restrict__ wt, float* __restrict__ y) {
    __shared__ float swt[TMAX * 8];
    int bf = blockIdx.x;
    int b = bf >> 5, f = bf & 31;
    int t = threadIdx.x;  // h
    const float* src = wt + (size_t)bf * (T * 8);
    for (int i = t; i < T * 8; i += 128) swt[i] = src[i];
    __syncthreads();
    if (t < 121) {
        float acc = cb[f];
        for (int tt = 0; tt < T; tt++) {
            const float* er = emb + tt * EMBD;
            #pragma unroll
            for (int k = 0; k < 8; k++) acc += swt[tt * 8 + k] * er[t + k];
        }
        y[b * FCIN + f * 121 + t] = acc;
    }
}

// ---------------- RNA: single fc on 0.5*(yG+yL) ----------------
__global__ void k_fc(const float* __restrict__ fw, const float* __restrict__ fb,
                     float* __restrict__ out) {
    __shared__ float sy[FCIN];
    int b = blockIdx.x, t = threadIdx.x;
    for (int i = t; i < FCIN; i += 128)
        sy[i] = 0.5f * (g_yG[b * FCIN + i] + g_yL[b * FCIN + i]);
    __syncthreads();
    float a0 = 0.f, a1 = 0.f, a2 = 0.f, a3 = 0.f;
    #pragma unroll 4
    for (int i = 0; i < FCIN; i += 4) {
        a0 = fmaf(sy[i + 0], fw[(i + 0) * EMBD + t], a0);
        a1 = fmaf(sy[i + 1], fw[(i + 1) * EMBD + t], a1);
        a2 = fmaf(sy[i + 2], fw[(i + 2) * EMBD + t], a2);
        a3 = fmaf(sy[i + 3], fw[(i + 3) * EMBD + t], a3);
    }
    out[b * EMBD + t] = fb[t] + ((a0 + a1) + (a2 + a3));
}

// ---------------- launch ----------------
extern "C" void kernel_launch(void* const* d_in, const int* in_sizes, int n_in,
                              void* d_out, int out_size) {
    const float* px   = (const float*)d_in[0];
    const int*   ei   = (const int*)d_in[1];
    const float* pw   = (const float*)d_in[2];
    const int*   pbat = (const int*)d_in[3];
    const int*   rg   = (const int*)d_in[4];
    const int*   rl   = (const int*)d_in[5];
    const float* g1w1 = (const float*)d_in[6];
    const float* g1b1 = (const float*)d_in[7];
    const float* g1w2 = (const float*)d_in[8];
    const float* g1b2 = (const float*)d_in[9];
    const float* g1ew = (const float*)d_in[10];
    const float* g1eb = (const float*)d_in[11];
    const float* g1ep = (const float*)d_in[12];
    const float* gw1  = (const float*)d_in[13];
    const float* gb1  = (const float*)d_in[14];
    const float* gw2  = (const float*)d_in[15];
    const float* gb2  = (const float*)d_in[16];
    const float* gew  = (const float*)d_in[17];
    const float* geb  = (const float*)d_in[18];
    const float* gep  = (const float*)d_in[19];
    const float* bng  = (const float*)d_in[20];
    const float* bnb  = (const float*)d_in[21];
    const float* fxpw = (const float*)d_in[22];
    const float* fxpb = (const float*)d_in[23];
    const float* emb1 = (const float*)d_in[24];
    const float* emb2 = (const float*)d_in[25];
    const float* c1w  = (const float*)d_in[26];
    const float* c1b  = (const float*)d_in[27];
    const float* c2w  = (const float*)d_in[28];
    const float* c2b  = (const float*)d_in[29];
    const float* fxw  = (const float*)d_in[30];
    const float* fxb  = (const float*)d_in[31];
    float* out = (float*)d_out;

    const int NB_SCAN = (NN + 1 + 1023) / 1024;  // 98

    float* wtG; cudaGetSymbolAddress((void**)&wtG, g_wtG);
    float* wtL; cudaGetSymbolAddress((void**)&wtL, g_wtL);
    float* yG;  cudaGetSymbolAddress((void**)&yG,  g_yG);
    float* yL;  cudaGetSymbolAddress((void**)&yL,  g_yL);
    int* blG;   cudaGetSymbolAddress((void**)&blG, g_blistG);
    int* blL;   cudaGetSymbolAddress((void**)&blL, g_blistL);
    int* boG;   cudaGetSymbolAddress((void**)&boG, g_boffG);
    int* boL;   cudaGetSymbolAddress((void**)&boL, g_boffL);

    k_init<<<128, 256>>>();
    k_pad<<<256, 256>>>(px);
    k_hist<<<1024, 256>>>(ei);
    k_scan1<<<NB_SCAN, 1024>>>();
    k_scan2<<<1, 128>>>(NB_SCAN);
    k_scan3<<<NB_SCAN, 1024>>>();
    k_scatter<<<1024, 256>>>(ei, pw);

    // RNA branches
    k_bucket<<<BGR, 256>>>(rg, LG, 5, blG, boG);
    k_bucket<<<BGR, 256>>>(rl, LL, TMAX, blL, boL);
    k_wtilde2<<<BGR * NFILT, 256>>>(c1w, blG, boG, LG, 5, 6, wtG);
    k_wtilde2<<<BGR * NFILT, 256>>>(c2w, blL, boL, LL, TMAX, 1, wtL);
    k_convy<<<BGR * NFILT, 128>>>(emb1, c1b, 5, wtG, yG);
    k_convy<<<BGR * NFILT, 128>>>(emb2, c2b, TMAX, wtL, yL);
    k_fc<<<BGR, 128>>>(fxw, fxb, out);

    // Protein GINE stack
    k_gine33<<<1184, 256>>>(g1w1, g1b1, g1w2, g1b2, g1ew, g1eb, g1ep);
    k_bnfinal<<<1, 32>>>(bng, bnb);
    for (int i = 0; i < 4; i++) {
        k_gine16<<<1184, 256>>>(gw1 + i * 256, gb1 + i * 16,
                                gw2 + i * 256, gb2 + i * 16,
                                gew + i * 16,  geb + i * 16,
                                gep + i, i & 1);
        k_bnfinal<<<1, 32>>>(bng + (i + 1) * 16, bnb + (i + 1) * 16);
    }
    k_pool<<<296, 256>>>(pbat);
    k_head<<<BGR, 128>>>(pbat, fxpw, fxpb, out);
}

// round 3
// speedup vs baseline: 2.7013x; 1.2005x over previous
#include <cuda_runtime.h>

#define NN     100000
#define NE     3200000
#define BGR    64
#define DIM    16
#define NFP    33
#define EMBD   128
#define LG     3000
#define LL     2998
#define NFILT  32
#define FCIN   3872    // 32*121
#define TMAX   65
#define FULL   0xffffffffu

// ---------------- device scratch (static, no allocation) ----------------
__device__ int    g_off[NN + 1];
__device__ int    g_cur[NN];
__device__ int2   g_csr[NE];           // .x = src, .y = float bits of w
__device__ float4 g_xb0[NN * 4];       // 16 floats per node
__device__ float4 g_xb1[NN * 4];
__device__ float4 g_pxp[NN * 9];       // padded 36-dim copy of pro_x
__device__ double g_stats[32];         // [0:16) sum, [16:32) sumsq
__device__ float  g_affine[32];        // [0:16) scale a, [16:32) shift b
__device__ float  g_pool[BGR * DIM];
__device__ int    g_bsum[128];
__device__ int    g_bpref[128];
__device__ int    g_boffG[BGR * (TMAX + 1)];
__device__ int    g_boffL[BGR * (TMAX + 1)];
__device__ int    g_blistG[BGR * LG];
__device__ int    g_blistL[BGR * LL];
__device__ float  g_wtG[BGR * NFILT * 5 * 8];
__device__ float  g_wtL[BGR * NFILT * TMAX * 8];
__device__ float  g_yG[BGR * FCIN];
__device__ float  g_yL[BGR * FCIN];

// ---------------- init ----------------
__global__ void k_init() {
    int i  = blockIdx.x * blockDim.x + threadIdx.x;
    int st = gridDim.x * blockDim.x;
    for (int j = i; j <= NN; j += st) g_off[j] = 0;
    if (i < 32) g_stats[i] = 0.0;
    for (int j = i; j < BGR * DIM; j += st) g_pool[j] = 0.f;
}

// ---------------- pad pro_x to 36 dims (float4-aligned rows) ----------------
__global__ void k_pad(const float* __restrict__ px) {
    int i  = blockIdx.x * blockDim.x + threadIdx.x;
    int st = gridDim.x * blockDim.x;
    float* o = (float*)g_pxp;
    for (int idx = i; idx < NN * 36; idx += st) {
        int n = idx / 36, d = idx - n * 36;
        o[idx] = (d < NFP) ? px[n * NFP + d] : 0.f;
    }
}

// ---------------- CSR build ----------------
__global__ void k_hist(const int* __restrict__ ei) {
    int i  = blockIdx.x * blockDim.x + threadIdx.x;
    int st = gridDim.x * blockDim.x;
    for (int e = i; e < NE; e += st) atomicAdd(&g_off[ei[NE + e] + 1], 1);
}

__global__ void k_scan1() {
    __shared__ int s[1024];
    int i = blockIdx.x * 1024 + threadIdx.x;
    int v = (i <= NN) ? g_off[i] : 0;
    s[threadIdx.x] = v;
    __syncthreads();
    for (int ofs = 1; ofs < 1024; ofs <<= 1) {
        int add = (threadIdx.x >= ofs) ? s[threadIdx.x - ofs] : 0;
        __syncthreads();
        s[threadIdx.x] += add;
        __syncthreads();
    }
    if (i <= NN) g_off[i] = s[threadIdx.x];
    if (threadIdx.x == 1023) g_bsum[blockIdx.x] = s[1023];
}

__global__ void k_scan2(int nb) {
    __shared__ int s[128];
    int t = threadIdx.x;
    int v = (t < nb) ? g_bsum[t] : 0;
    s[t] = v;
    __syncthreads();
    for (int ofs = 1; ofs < 128; ofs <<= 1) {
        int add = (t >= ofs) ? s[t - ofs] : 0;
        __syncthreads();
        s[t] += add;
        __syncthreads();
    }
    if (t < nb) g_bpref[t] = s[t] - v;   // exclusive
}

__global__ void k_scan3() {
    int i = blockIdx.x * 1024 + threadIdx.x;
    if (i <= NN) {
        int v = g_off[i] + g_bpref[blockIdx.x];
        g_off[i] = v;
        if (i < NN) g_cur[i] = v;
    }
}

__global__ void k_scatter(const int* __restrict__ ei, const float* __restrict__ pw) {
    int i  = blockIdx.x * blockDim.x + threadIdx.x;
    int st = gridDim.x * blockDim.x;
    for (int e = i; e < NE; e += st) {
        int src = ei[e];
        int dst = ei[NE + e];
        int p   = atomicAdd(&g_cur[dst], 1);
        g_csr[p] = make_int2(src, __float_as_int(pw[e]));
    }
}

// ---------------- GINE layer 1 (33 -> 16): 8 edges in flight, prefetched ----------------
__global__ void k_gine33(const float* __restrict__ W1, const float* __restrict__ b1,
                         const float* __restrict__ W2, const float* __restrict__ b2,
                         const float* __restrict__ ew, const float* __restrict__ ebv,
                         const float* __restrict__ epsp) {
    __shared__ float sW1[NFP * 16], sW2[256], sb1[16], sb2[16], sc[36], se[36];
    __shared__ float ssum[16], ssq[16];
    int t = threadIdx.x;
    for (int i = t; i < NFP * 16; i += 256) sW1[i] = W1[i];
    for (int i = t; i < 256; i += 256) sW2[i] = W2[i];
    if (t < 16) { sb1[t] = b1[t]; sb2[t] = b2[t]; ssum[t] = 0.f; ssq[t] = 0.f; }
    if (t < 36) { sc[t] = (t < NFP) ? ew[t] : 0.f; se[t] = (t < NFP) ? ebv[t] : 0.f; }
    __syncthreads();
    float ope = 1.f + epsp[0];
    int lane  = t & 31;
    int eslot = lane >> 2, q = lane & 3;
    float cA0 = sc[q*4+0], cA1 = sc[q*4+1], cA2 = sc[q*4+2], cA3 = sc[q*4+3];
    float eA0 = se[q*4+0], eA1 = se[q*4+1], eA2 = se[q*4+2], eA3 = se[q*4+3];
    float cB0 = sc[(q+4)*4+0], cB1 = sc[(q+4)*4+1], cB2 = sc[(q+4)*4+2], cB3 = sc[(q+4)*4+3];
    float eB0 = se[(q+4)*4+0], eB1 = se[(q+4)*4+1], eB2 = se[(q+4)*4+2], eB3 = se[(q+4)*4+3];
    float c32 = sc[32], e32 = se[32];
    int gw = blockIdx.x * 8 + (t >> 5);
    int nw = gridDim.x * 8;
    float lsum = 0.f, lsq = 0.f;
    for (int n = gw; n < NN; n += nw) {
        int beg = g_off[n], end = g_off[n + 1];
        float ax=0,ay=0,az=0,aw=0, bx=0,by=0,bz=0,bw=0, a32=0;
        int j = beg + eslot;
        bool have = j < end;
        int2 swc = have ? __ldg(&g_csr[j]) : make_int2(0, 0);
        while (have) {
            int jn = j + 8;
            bool hn = jn < end;
            int2 swn = hn ? __ldg(&g_csr[jn]) : make_int2(0, 0);
            int   src = swc.x;
            float wv  = __int_as_float(swc.y);
            const float4* row = g_pxp + src * 9;
            float4 xa = __ldg(row + q);
            float4 xb = __ldg(row + q + 4);
            ax += fmaxf(xa.x + fmaf(wv, cA0, eA0), 0.f);
            ay += fmaxf(xa.y + fmaf(wv, cA1, eA1), 0.f);
            az += fmaxf(xa.z + fmaf(wv, cA2, eA2), 0.f);
            aw += fmaxf(xa.w + fmaf(wv, cA3, eA3), 0.f);
            bx += fmaxf(xb.x + fmaf(wv, cB0, eB0), 0.f);
            by += fmaxf(xb.y + fmaf(wv, cB1, eB1), 0.f);
            bz += fmaxf(xb.z + fmaf(wv, cB2, eB2), 0.f);
            bw += fmaxf(xb.w + fmaf(wv, cB3, eB3), 0.f);
            if (q == 0) {
                float x32 = __ldg(((const float*)row) + 32);
                a32 += fmaxf(x32 + fmaf(wv, c32, e32), 0.f);
            }
            swc = swn; j = jn; have = hn;
        }
        #pragma unroll
        for (int ofs = 4; ofs < 32; ofs <<= 1) {
            ax += __shfl_xor_sync(FULL, ax, ofs); ay += __shfl_xor_sync(FULL, ay, ofs);
            az += __shfl_xor_sync(FULL, az, ofs); aw += __shfl_xor_sync(FULL, aw, ofs);
            bx += __shfl_xor_sync(FULL, bx, ofs); by += __shfl_xor_sync(FULL, by, ofs);
            bz += __shfl_xor_sync(FULL, bz, ofs); bw += __shfl_xor_sync(FULL, bw, ofs);
            a32 += __shfl_xor_sync(FULL, a32, ofs);
        }
        int srcl = (lane >> 2) & 3;
        float vax = __shfl_sync(FULL, ax, srcl), vay = __shfl_sync(FULL, ay, srcl);
        float vaz = __shfl_sync(FULL, az, srcl), vaw = __shfl_sync(FULL, aw, srcl);
        float vbx = __shfl_sync(FULL, bx, srcl), vby = __shfl_sync(FULL, by, srcl);
        float vbz = __shfl_sync(FULL, bz, srcl), vbw = __shfl_sync(FULL, bw, srcl);
        float gx = (lane >= 16) ? vbx : vax;
        float gy = (lane >= 16) ? vby : vay;
        float gz = (lane >= 16) ? vbz : vaz;
        float gwv = (lane >= 16) ? vbw : vaw;
        float lo = (lane & 1) ? gy : gx;
        float hi = (lane & 1) ? gwv : gz;
        float aggv = (lane & 2) ? hi : lo;
        float agg32 = __shfl_sync(FULL, a32, 0);
        const float* nrow = (const float*)(g_pxp + n * 9);
        float h   = ope * nrow[lane] + aggv;   // dims 0..31
        float h32 = ope * nrow[32] + agg32;
        float tj = (lane < 16) ? sb1[lane] : 0.f;
        #pragma unroll
        for (int d = 0; d < 32; d++) {
            float hd = __shfl_sync(FULL, h, d);
            if (lane < 16) tj = fmaf(hd, sW1[d * 16 + lane], tj);
        }
        if (lane < 16) tj = fmaf(h32, sW1[32 * 16 + lane], tj);
        tj = fmaxf(tj, 0.f);
        float oj = (lane < 16) ? sb2[lane] : 0.f;
        #pragma unroll
        for (int d = 0; d < 16; d++) {
            float td = __shfl_sync(FULL, tj, d);
            if (lane < 16) oj = fmaf(td, sW2[d * 16 + lane], oj);
        }
        if (lane < 16) {
            float y = fmaxf(oj, 0.f);
            ((float*)g_xb0)[n * DIM + lane] = y;
            lsum += y; lsq += y * y;
        }
    }
    if (lane < 16) { atomicAdd(&ssum[lane], lsum); atomicAdd(&ssq[lane], lsq); }
    __syncthreads();
    if (t < 16) {
        atomicAdd(&g_stats[t],      (double)ssum[t]);
        atomicAdd(&g_stats[16 + t], (double)ssq[t]);
    }
}

// ---------------- BN finalize ----------------
__global__ void k_bnfinal(const float* __restrict__ gamma, const float* __restrict__ beta) {
    int t = threadIdx.x;
    if (t < 16) {
        double s = g_stats[t], q = g_stats[16 + t];
        float mu  = (float)(s / (double)NN);
        float var = (float)(q / (double)NN) - mu * mu;
        float a   = gamma[t] * rsqrtf(fmaxf(var, 0.f) + 1e-5f);
        g_affine[t]      = a;
        g_affine[16 + t] = beta[t] - mu * a;
    }
    if (t < 32) g_stats[t] = 0.0;
}

// ---------------- GINE layers 2..5 (16 -> 16): prefetched edge loop ----------------
__global__ void k_gine16(const float* __restrict__ W1, const float* __restrict__ b1,
                         const float* __restrict__ W2, const float* __restrict__ b2,
                         const float* __restrict__ ew, const float* __restrict__ ebv,
                         const float* __restrict__ epsp, int flip) {
    const float4* xin4 = flip ? g_xb1 : g_xb0;
    float*        xout = (float*)(flip ? g_xb0 : g_xb1);
    const float*  xin  = (const float*)xin4;
    __shared__ float sW1[256], sW2[256], sb1[16], sb2[16], sc[16], se[16], sa[16], sbb[16];
    __shared__ float ssum[16], ssq[16];
    int t = threadIdx.x;
    for (int i = t; i < 256; i += 256) { sW1[i] = W1[i]; sW2[i] = W2[i]; }
    if (t < 16) {
        sb1[t] = b1[t]; sb2[t] = b2[t]; sc[t] = ew[t]; se[t] = ebv[t];
        sa[t] = g_affine[t]; sbb[t] = g_affine[16 + t];
        ssum[t] = 0.f; ssq[t] = 0.f;
    }
    __syncthreads();
    float ope = 1.f + epsp[0];
    int lane  = t & 31;
    int eslot = lane >> 2, q = lane & 3;
    float a0 = sa[q*4+0], a1 = sa[q*4+1], a2 = sa[q*4+2], a3 = sa[q*4+3];
    float p0 = sbb[q*4+0], p1 = sbb[q*4+1], p2 = sbb[q*4+2], p3 = sbb[q*4+3];
    float c0 = sc[q*4+0], c1 = sc[q*4+1], c2 = sc[q*4+2], c3 = sc[q*4+3];
    float e0 = se[q*4+0], e1 = se[q*4+1], e2 = se[q*4+2], e3 = se[q*4+3];
    int gw = blockIdx.x * 8 + (t >> 5);
    int nw = gridDim.x * 8;
    float lsum = 0.f, lsq = 0.f;
    for (int n = gw; n < NN; n += nw) {
        int beg = g_off[n], end = g_off[n + 1];
        float ax = 0.f, ay = 0.f, az = 0.f, aw = 0.f;
        int j = beg + eslot;
        bool have = j < end;
        int2 swc = have ? __ldg(&g_csr[j]) : make_int2(0, 0);
        while (have) {
            int jn = j + 8;
            bool hn = jn < end;
            int2 swn = hn ? __ldg(&g_csr[jn]) : make_int2(0, 0);
            int   src = swc.x;
            float wv  = __int_as_float(swc.y);
            float4 xv = __ldg(&xin4[src * 4 + q]);
            ax += fmaxf(fmaf(a0, xv.x, p0) + fmaf(wv, c0, e0), 0.f);
            ay += fmaxf(fmaf(a1, xv.y, p1) + fmaf(wv, c1, e1), 0.f);
            az += fmaxf(fmaf(a2, xv.z, p2) + fmaf(wv, c2, e2), 0.f);
            aw += fmaxf(fmaf(a3, xv.w, p3) + fmaf(wv, c3, e3), 0.f);
            swc = swn; j = jn; have = hn;
        }
        #pragma unroll
        for (int ofs = 4; ofs < 32; ofs <<= 1) {
            ax += __shfl_xor_sync(FULL, ax, ofs); ay += __shfl_xor_sync(FULL, ay, ofs);
            az += __shfl_xor_sync(FULL, az, ofs); aw += __shfl_xor_sync(FULL, aw, ofs);
        }
        float vx = __shfl_sync(FULL, ax, lane >> 2);
        float vy = __shfl_sync(FULL, ay, lane >> 2);
        float vz = __shfl_sync(FULL, az, lane >> 2);
        float vw = __shfl_sync(FULL, aw, lane >> 2);
        float lo = (lane & 1) ? vy : vx;
        float hi = (lane & 1) ? vw : vz;
        float aggv = (lane & 2) ? hi : lo;
        float h = 0.f;
        if (lane < 16) {
            float xn = fmaf(sa[lane], xin[n * DIM + lane], sbb[lane]);
            h = ope * xn + aggv;
        }
        float tj = (lane < 16) ? sb1[lane] : 0.f;
        #pragma unroll
        for (int dd = 0; dd < 16; dd++) {
            float hd = __shfl_sync(FULL, h, dd);
            if (lane < 16) tj = fmaf(hd, sW1[dd * 16 + lane], tj);
        }
        tj = fmaxf(tj, 0.f);
        float oj = (lane < 16) ? sb2[lane] : 0.f;
        #pragma unroll
        for (int dd = 0; dd < 16; dd++) {
            float td = __shfl_sync(FULL, tj, dd);
            if (lane < 16) oj = fmaf(td, sW2[dd * 16 + lane], oj);
        }
        if (lane < 16) {
            float y = fmaxf(oj, 0.f);
            xout[n * DIM + lane] = y;
            lsum += y; lsq += y * y;
        }
    }
    if (lane < 16) { atomicAdd(&ssum[lane], lsum); atomicAdd(&ssq[lane], lsq); }
    __syncthreads();
    if (t < 16) {
        atomicAdd(&g_stats[t],      (double)ssum[t]);
        atomicAdd(&g_stats[16 + t], (double)ssq[t]);
    }
}

// ---------------- global mean pool ----------------
__global__ void k_pool(const int* __restrict__ batch) {
    __shared__ float sp[BGR * DIM];
    __shared__ float sa[16], sbb[16];
    int t = threadIdx.x;
    for (int i = t; i < BGR * DIM; i += 256) sp[i] = 0.f;
    if (t < 16) { sa[t] = g_affine[t]; sbb[t] = g_affine[16 + t]; }
    __syncthreads();
    int st = gridDim.x * 256;
    const float* xb = (const float*)g_xb0;
    for (int idx = blockIdx.x * 256 + t; idx < NN * DIM; idx += st) {
        int n = idx >> 4, dd = idx & 15;
        int bt = batch[n];
        float v = fmaf(sa[dd], xb[idx], sbb[dd]);
        atomicAdd(&sp[bt * DIM + dd], v);
    }
    __syncthreads();
    for (int i = t; i < BGR * DIM; i += 256) atomicAdd(&g_pool[i], sp[i]);
}

__device__ __forceinline__ int lbound(const int* a, int n, int key) {
    int lo = 0, hi = n;
    while (lo < hi) { int mid = (lo + hi) >> 1; if (a[mid] < key) lo = mid + 1; else hi = mid; }
    return lo;
}

__global__ void k_head(const int* __restrict__ batch,
                       const float* __restrict__ fw, const float* __restrict__ fb,
                       float* __restrict__ out) {
    __shared__ float sm[16];
    __shared__ int scnt;
    int b = blockIdx.x, t = threadIdx.x;
    if (t == 0) {
        int lo = lbound(batch, NN, b);
        int hi = lbound(batch, NN, b + 1);
        scnt = max(hi - lo, 1);
    }
    __syncthreads();
    if (t < 16) sm[t] = g_pool[b * DIM + t] / (float)scnt;
    __syncthreads();
    float acc = fb[t];
    #pragma unroll
    for (int dd = 0; dd < 16; dd++) acc += sm[dd] * fw[dd * EMBD + t];
    out[BGR * EMBD + b * EMBD + t] = fmaxf(acc, 0.f);
}

// ---------------- RNA: bucket build per batch row ----------------
__global__ void k_bucket(const int* __restrict__ tok, int L, int T,
                         int* __restrict__ list, int* __restrict__ boff) {
    __shared__ int cnt[TMAX + 1];
    __shared__ int offs[TMAX + 1];
    int b = blockIdx.x, t = threadIdx.x;
    if (t <= T) cnt[t] = 0;
    __syncthreads();
    const int* tb = tok + b * L;
    for (int c = t; c < L; c += 256) atomicAdd(&cnt[tb[c]], 1);
    __syncthreads();
    if (t == 0) {
        int acc = 0;
        for (int i = 0; i < T; i++) { offs[i] = acc; acc += cnt[i]; }
        offs[T] = acc;
    }
    __syncthreads();
    if (t <= T) boff[b * (TMAX + 1) + t] = offs[t];
    if (t < T) cnt[t] = offs[t];   // reuse as cursors
    __syncthreads();
    for (int c = t; c < L; c += 256) {
        int pos = atomicAdd(&cnt[tb[c]], 1);
        list[b * L + pos] = c;
    }
}

// ---------------- RNA: W~[b,f,t,k] — warp-per-bucket, coalesced 32B tap reads ----------------
__global__ void k_wtilde3(const float* __restrict__ w,
                          const int* __restrict__ list, const int* __restrict__ boff,
                          int L, int T, float* __restrict__ wt) {
    __shared__ int soff[TMAX + 1];
    int bf = blockIdx.x;
    int b = bf >> 5, f = bf & 31;
    int tid = threadIdx.x;
    if (tid <= T) soff[tid] = boff[b * (TMAX + 1) + tid];
    __syncthreads();
    const int*   lst = list + b * L;
    const float* wf  = w + (size_t)f * L * 8;
    float* o = wt + (size_t)bf * (T * 8);
    int wid = tid >> 5, lane = tid & 31;
    int pg = lane >> 3, k = lane & 7;   // 4 position groups x 8 taps
    for (int tt = wid; tt < T; tt += 8) {
        int lo = soff[tt], hi = soff[tt + 1];
        float acc = 0.f;
        for (int p = lo + pg; p < hi; p += 4) {
            int c = __ldg(&lst[p]);
            acc += __ldg(&wf[c * 8 + k]);
        }
        acc += __shfl_xor_sync(FULL, acc, 8);
        acc += __shfl_xor_sync(FULL, acc, 16);
        if (lane < 8) o[tt * 8 + k] = acc;
    }
}

// ---------------- RNA: y[b,f,h] = cb[f] + sum_{t,k} W~ * emb[t,h+k] ----------------
__global__ void k_convy(const float* __restrict__ emb, const float* __restrict__ cb,
                        int T, const float* __restrict__ wt, float* __restrict__ y) {
    __shared__ float swt[TMAX * 8];
    int bf = blockIdx.x;
    int b = bf >> 5, f = bf & 31;
    int t = threadIdx.x;  // h
    const float* src = wt + (size_t)bf * (T * 8);
    for (int i = t; i < T * 8; i += 128) swt[i] = src[i];
    __syncthreads();
    if (t < 121) {
        float acc0 = cb[f], acc1 = 0.f;
        for (int tt = 0; tt < T; tt++) {
            const float* er = emb + tt * EMBD;
            acc0 = fmaf(swt[tt*8+0], er[t+0], acc0);
            acc1 = fmaf(swt[tt*8+1], er[t+1], acc1);
            acc0 = fmaf(swt[tt*8+2], er[t+2], acc0);
            acc1 = fmaf(swt[tt*8+3], er[t+3], acc1);
            acc0 = fmaf(swt[tt*8+4], er[t+4], acc0);
            acc1 = fmaf(swt[tt*8+5], er[t+5], acc1);
            acc0 = fmaf(swt[tt*8+6], er[t+6], acc0);
            acc1 = fmaf(swt[tt*8+7], er[t+7], acc1);
        }
        y[b * FCIN + f * 121 + t] = acc0 + acc1;
    }
}

// ---------------- RNA: single fc on 0.5*(yG+yL), 4-way split over FCIN ----------------
__global__ void k_fc(const float* __restrict__ fw, const float* __restrict__ fb,
                     float* __restrict__ out) {
    __shared__ float sy[FCIN];
    __shared__ float sred[4][EMBD];
    int b = blockIdx.x, tid = threadIdx.x;
    for (int i = tid; i < FCIN; i += 512)
        sy[i] = 0.5f * (g_yG[b * FCIN + i] + g_yL[b * FCIN + i]);
    __syncthreads();
    int t = tid & 127, chunk = tid >> 7;
    int lo = chunk * (FCIN / 4), hi = lo + (FCIN / 4);
    float a0 = 0.f, a1 = 0.f;
    for (int i = lo; i < hi; i += 2) {
        a0 = fmaf(sy[i + 0], __ldg(&fw[(i + 0) * EMBD + t]), a0);
        a1 = fmaf(sy[i + 1], __ldg(&fw[(i + 1) * EMBD + t]), a1);
    }
    sred[chunk][t] = a0 + a1;
    __syncthreads();
    if (tid < 128)
        out[b * EMBD + tid] = fb[tid] +
            ((sred[0][tid] + sred[1][tid]) + (sred[2][tid] + sred[3][tid]));
}

// ---------------- launch ----------------
extern "C" void kernel_launch(void* const* d_in, const int* in_sizes, int n_in,
                              void* d_out, int out_size) {
    const float* px   = (const float*)d_in[0];
    const int*   ei   = (const int*)d_in[1];
    const float* pw   = (const float*)d_in[2];
    const int*   pbat = (const int*)d_in[3];
    const int*   rg   = (const int*)d_in[4];
    const int*   rl   = (const int*)d_in[5];
    const float* g1w1 = (const float*)d_in[6];
    const float* g1b1 = (const float*)d_in[7];
    const float* g1w2 = (const float*)d_in[8];
    const float* g1b2 = (const float*)d_in[9];
    const float* g1ew = (const float*)d_in[10];
    const float* g1eb = (const float*)d_in[11];
    const float* g1ep = (const float*)d_in[12];
    const float* gw1  = (const float*)d_in[13];
    const float* gb1  = (const float*)d_in[14];
    const float* gw2  = (const float*)d_in[15];
    const float* gb2  = (const float*)d_in[16];
    const float* gew  = (const float*)d_in[17];
    const float* geb  = (const float*)d_in[18];
    const float* gep  = (const float*)d_in[19];
    const float* bng  = (const float*)d_in[20];
    const float* bnb  = (const float*)d_in[21];
    const float* fxpw = (const float*)d_in[22];
    const float* fxpb = (const float*)d_in[23];
    const float* emb1 = (const float*)d_in[24];
    const float* emb2 = (const float*)d_in[25];
    const float* c1w  = (const float*)d_in[26];
    const float* c1b  = (const float*)d_in[27];
    const float* c2w  = (const float*)d_in[28];
    const float* c2b  = (const float*)d_in[29];
    const float* fxw  = (const float*)d_in[30];
    const float* fxb  = (const float*)d_in[31];
    float* out = (float*)d_out;

    const int NB_SCAN = (NN + 1 + 1023) / 1024;  // 98

    float* wtG; cudaGetSymbolAddress((void**)&wtG, g_wtG);
    float* wtL; cudaGetSymbolAddress((void**)&wtL, g_wtL);
    float* yG;  cudaGetSymbolAddress((void**)&yG,  g_yG);
    float* yL;  cudaGetSymbolAddress((void**)&yL,  g_yL);
    int* blG;   cudaGetSymbolAddress((void**)&blG, g_blistG);
    int* blL;   cudaGetSymbolAddress((void**)&blL, g_blistL);
    int* boG;   cudaGetSymbolAddress((void**)&boG, g_boffG);
    int* boL;   cudaGetSymbolAddress((void**)&boL, g_boffL);

    // RNA branch first (also positions the hot local-wtilde at snapshot index 3)
    k_init<<<128, 256>>>();                                   // 0
    k_bucket<<<BGR, 256>>>(rg, LG, 5, blG, boG);              // 1
    k_bucket<<<BGR, 256>>>(rl, LL, TMAX, blL, boL);           // 2
    k_wtilde3<<<BGR * NFILT, 256>>>(c2w, blL, boL, LL, TMAX, wtL);  // 3 <- profile target
    k_wtilde3<<<BGR * NFILT, 256>>>(c1w, blG, boG, LG, 5, wtG);     // 4
    k_convy<<<BGR * NFILT, 128>>>(emb1, c1b, 5, wtG, yG);     // 5
    k_convy<<<BGR * NFILT, 128>>>(emb2, c2b, TMAX, wtL, yL);  // 6
    k_fc<<<BGR, 512>>>(fxw, fxb, out);                        // 7

    // CSR build
    k_pad<<<256, 256>>>(px);
    k_hist<<<1024, 256>>>(ei);
    k_scan1<<<NB_SCAN, 1024>>>();
    k_scan2<<<1, 128>>>(NB_SCAN);
    k_scan3<<<NB_SCAN, 1024>>>();
    k_scatter<<<1024, 256>>>(ei, pw);

    // Protein GINE stack
    k_gine33<<<1184, 256>>>(g1w1, g1b1, g1w2, g1b2, g1ew, g1eb, g1ep);
    k_bnfinal<<<1, 32>>>(bng, bnb);
    for (int i = 0; i < 4; i++) {
        k_gine16<<<1184, 256>>>(gw1 + i * 256, gb1 + i * 16,
                                gw2 + i * 256, gb2 + i * 16,
                                gew + i * 16,  geb + i * 16,
                                gep + i, i & 1);
        k_bnfinal<<<1, 32>>>(bng + (i + 1) * 16, bnb + (i + 1) * 16);
    }
    k_pool<<<296, 256>>>(pbat);
    k_head<<<BGR, 128>>>(pbat, fxpw, fxpb, out);
}

// round 4
// speedup vs baseline: 3.5424x; 1.3114x over previous
#include <cuda_runtime.h>

#define NN     100000
#define NE     3200000
#define BGR    64
#define DIM    16
#define NFP    33
#define EMBD   128
#define LG     3000
#define LL     2998
#define NFILT  32
#define FCIN   3872    // 32*121
#define TMAX   65
#define FULL   0xffffffffu

// ---------------- device scratch (static, no allocation) ----------------
__device__ int    g_off[NN + 1];
__device__ int    g_cur[NN];
__device__ int2   g_csr[NE];           // .x = src, .y = float bits of w
__device__ float4 g_xb0[NN * 4];       // 16 floats per node
__device__ float4 g_xb1[NN * 4];
__device__ float4 g_pxp[NN * 9];       // padded 36-dim copy of pro_x
__device__ double g_stats5[5 * 32];    // per-layer: [0:16) sum, [16:32) sumsq
__device__ float  g_pool[BGR * DIM];
__device__ int    g_bsum[128];
__device__ int    g_boffG[BGR * (TMAX + 1)];
__device__ int    g_boffL[BGR * (TMAX + 1)];
__device__ int    g_blistG[BGR * LG];
__device__ int    g_blistL[BGR * LL];
__device__ float  g_wtG[BGR * NFILT * 5 * 8];
__device__ float  g_wtL[BGR * NFILT * TMAX * 8];
__device__ float  g_yG[BGR * FCIN];
__device__ float  g_yL[BGR * FCIN];

// ---------------- init (protein-side scratch) ----------------
__global__ void k_initA() {
    int i  = blockIdx.x * blockDim.x + threadIdx.x;
    int st = gridDim.x * blockDim.x;
    for (int j = i; j <= NN; j += st) g_off[j] = 0;
    if (i < 5 * 32) g_stats5[i] = 0.0;
    for (int j = i; j < BGR * DIM; j += st) g_pool[j] = 0.f;
}

// ---------------- pad pro_x (36-dim rows) + degree histogram, fused ----------------
__global__ void k_padhist(const float* __restrict__ px, const int* __restrict__ ei) {
    int i  = blockIdx.x * blockDim.x + threadIdx.x;
    int st = gridDim.x * blockDim.x;
    float* o = (float*)g_pxp;
    for (int idx = i; idx < NN * 36; idx += st) {
        int n = idx / 36, d = idx - n * 36;
        o[idx] = (d < NFP) ? px[n * NFP + d] : 0.f;
    }
    for (int e = i; e < NE; e += st) atomicAdd(&g_off[ei[NE + e] + 1], 1);
}

__global__ void k_scan1() {
    __shared__ int s[1024];
    int i = blockIdx.x * 1024 + threadIdx.x;
    int v = (i <= NN) ? g_off[i] : 0;
    s[threadIdx.x] = v;
    __syncthreads();
    for (int ofs = 1; ofs < 1024; ofs <<= 1) {
        int add = (threadIdx.x >= ofs) ? s[threadIdx.x - ofs] : 0;
        __syncthreads();
        s[threadIdx.x] += add;
        __syncthreads();
    }
    if (i <= NN) g_off[i] = s[threadIdx.x];
    if (threadIdx.x == 1023) g_bsum[blockIdx.x] = s[1023];
}

// scan3 with inline cross-block prefix (replaces old scan2+scan3)
__global__ void k_scan3b() {
    __shared__ int sp;
    int t = threadIdx.x;
    if (t < 32) {
        int acc = 0;
        for (int k = t; k < blockIdx.x; k += 32) acc += g_bsum[k];
        #pragma unroll
        for (int ofs = 16; ofs > 0; ofs >>= 1) acc += __shfl_xor_sync(FULL, acc, ofs);
        if (t == 0) sp = acc;
    }
    __syncthreads();
    int i = blockIdx.x * 1024 + t;
    if (i <= NN) {
        int v = g_off[i] + sp;
        g_off[i] = v;
        if (i < NN) g_cur[i] = v;
    }
}

__global__ void k_scatter(const int* __restrict__ ei, const float* __restrict__ pw) {
    int i  = blockIdx.x * blockDim.x + threadIdx.x;
    int st = gridDim.x * blockDim.x;
    for (int e = i; e < NE; e += st) {
        int src = ei[e];
        int dst = ei[NE + e];
        int p   = atomicAdd(&g_cur[dst], 1);
        g_csr[p] = make_int2(src, __float_as_int(pw[e]));
    }
}

// ---------------- GINE layer 1 (33 -> 16): 8 edges in flight, prefetched ----------------
__global__ void k_gine33(const float* __restrict__ W1, const float* __restrict__ b1,
                         const float* __restrict__ W2, const float* __restrict__ b2,
                         const float* __restrict__ ew, const float* __restrict__ ebv,
                         const float* __restrict__ epsp) {
    __shared__ float sW1[NFP * 16], sW2[256], sb1[16], sb2[16], sc[36], se[36];
    __shared__ float ssum[16], ssq[16];
    int t = threadIdx.x;
    for (int i = t; i < NFP * 16; i += 256) sW1[i] = W1[i];
    for (int i = t; i < 256; i += 256) sW2[i] = W2[i];
    if (t < 16) { sb1[t] = b1[t]; sb2[t] = b2[t]; ssum[t] = 0.f; ssq[t] = 0.f; }
    if (t < 36) { sc[t] = (t < NFP) ? ew[t] : 0.f; se[t] = (t < NFP) ? ebv[t] : 0.f; }
    __syncthreads();
    float ope = 1.f + epsp[0];
    int lane  = t & 31;
    int eslot = lane >> 2, q = lane & 3;
    float cA0 = sc[q*4+0], cA1 = sc[q*4+1], cA2 = sc[q*4+2], cA3 = sc[q*4+3];
    float eA0 = se[q*4+0], eA1 = se[q*4+1], eA2 = se[q*4+2], eA3 = se[q*4+3];
    float cB0 = sc[(q+4)*4+0], cB1 = sc[(q+4)*4+1], cB2 = sc[(q+4)*4+2], cB3 = sc[(q+4)*4+3];
    float eB0 = se[(q+4)*4+0], eB1 = se[(q+4)*4+1], eB2 = se[(q+4)*4+2], eB3 = se[(q+4)*4+3];
    float c32 = sc[32], e32 = se[32];
    int gw = blockIdx.x * 8 + (t >> 5);
    int nw = gridDim.x * 8;
    float lsum = 0.f, lsq = 0.f;
    for (int n = gw; n < NN; n += nw) {
        int beg = g_off[n], end = g_off[n + 1];
        float ax=0,ay=0,az=0,aw=0, bx=0,by=0,bz=0,bw=0, a32=0;
        int j = beg + eslot;
        bool have = j < end;
        int2 swc = have ? __ldg(&g_csr[j]) : make_int2(0, 0);
        while (have) {
            int jn = j + 8;
            bool hn = jn < end;
            int2 swn = hn ? __ldg(&g_csr[jn]) : make_int2(0, 0);
            int   src = swc.x;
            float wv  = __int_as_float(swc.y);
            const float4* row = g_pxp + src * 9;
            float4 xa = __ldg(row + q);
            float4 xb = __ldg(row + q + 4);
            ax += fmaxf(xa.x + fmaf(wv, cA0, eA0), 0.f);
            ay += fmaxf(xa.y + fmaf(wv, cA1, eA1), 0.f);
            az += fmaxf(xa.z + fmaf(wv, cA2, eA2), 0.f);
            aw += fmaxf(xa.w + fmaf(wv, cA3, eA3), 0.f);
            bx += fmaxf(xb.x + fmaf(wv, cB0, eB0), 0.f);
            by += fmaxf(xb.y + fmaf(wv, cB1, eB1), 0.f);
            bz += fmaxf(xb.z + fmaf(wv, cB2, eB2), 0.f);
            bw += fmaxf(xb.w + fmaf(wv, cB3, eB3), 0.f);
            if (q == 0) {
                float x32 = __ldg(((const float*)row) + 32);
                a32 += fmaxf(x32 + fmaf(wv, c32, e32), 0.f);
            }
            swc = swn; j = jn; have = hn;
        }
        #pragma unroll
        for (int ofs = 4; ofs < 32; ofs <<= 1) {
            ax += __shfl_xor_sync(FULL, ax, ofs); ay += __shfl_xor_sync(FULL, ay, ofs);
            az += __shfl_xor_sync(FULL, az, ofs); aw += __shfl_xor_sync(FULL, aw, ofs);
            bx += __shfl_xor_sync(FULL, bx, ofs); by += __shfl_xor_sync(FULL, by, ofs);
            bz += __shfl_xor_sync(FULL, bz, ofs); bw += __shfl_xor_sync(FULL, bw, ofs);
            a32 += __shfl_xor_sync(FULL, a32, ofs);
        }
        int srcl = (lane >> 2) & 3;
        float vax = __shfl_sync(FULL, ax, srcl), vay = __shfl_sync(FULL, ay, srcl);
        float vaz = __shfl_sync(FULL, az, srcl), vaw = __shfl_sync(FULL, aw, srcl);
        float vbx = __shfl_sync(FULL, bx, srcl), vby = __shfl_sync(FULL, by, srcl);
        float vbz = __shfl_sync(FULL, bz, srcl), vbw = __shfl_sync(FULL, bw, srcl);
        float gx = (lane >= 16) ? vbx : vax;
        float gy = (lane >= 16) ? vby : vay;
        float gz = (lane >= 16) ? vbz : vaz;
        float gwv = (lane >= 16) ? vbw : vaw;
        float lo = (lane & 1) ? gy : gx;
        float hi = (lane & 1) ? gwv : gz;
        float aggv = (lane & 2) ? hi : lo;
        float agg32 = __shfl_sync(FULL, a32, 0);
        const float* nrow = (const float*)(g_pxp + n * 9);
        float h   = ope * nrow[lane] + aggv;   // dims 0..31
        float h32 = ope * nrow[32] + agg32;
        float tj = (lane < 16) ? sb1[lane] : 0.f;
        #pragma unroll
        for (int d = 0; d < 32; d++) {
            float hd = __shfl_sync(FULL, h, d);
            if (lane < 16) tj = fmaf(hd, sW1[d * 16 + lane], tj);
        }
        if (lane < 16) tj = fmaf(h32, sW1[32 * 16 + lane], tj);
        tj = fmaxf(tj, 0.f);
        float oj = (lane < 16) ? sb2[lane] : 0.f;
        #pragma unroll
        for (int d = 0; d < 16; d++) {
            float td = __shfl_sync(FULL, tj, d);
            if (lane < 16) oj = fmaf(td, sW2[d * 16 + lane], oj);
        }
        if (lane < 16) {
            float y = fmaxf(oj, 0.f);
            ((float*)g_xb0)[n * DIM + lane] = y;
            lsum += y; lsq += y * y;
        }
    }
    if (lane < 16) { atomicAdd(&ssum[lane], lsum); atomicAdd(&ssq[lane], lsq); }
    __syncthreads();
    if (t < 16) {
        atomicAdd(&g_stats5[t],      (double)ssum[t]);
        atomicAdd(&g_stats5[16 + t], (double)ssq[t]);
    }
}

// ---------------- GINE layers 2..5 (16 -> 16): 2 nodes/warp, per-block BN affine ----------------
__global__ void k_gine16(const float* __restrict__ W1, const float* __restrict__ b1,
                         const float* __restrict__ W2, const float* __restrict__ b2,
                         const float* __restrict__ ew, const float* __restrict__ ebv,
                         const float* __restrict__ epsp,
                         const float* __restrict__ gamma, const float* __restrict__ beta,
                         int layer, int flip) {
    const float4* xin4 = flip ? g_xb1 : g_xb0;
    float*        xout = (float*)(flip ? g_xb0 : g_xb1);
    const float*  xin  = (const float*)xin4;
    __shared__ float sW1[256], sW2[256], sb1[16], sb2[16], sc[16], se[16], sa[16], sbb[16];
    __shared__ float ssum[16], ssq[16];
    int t = threadIdx.x;
    for (int i = t; i < 256; i += 256) { sW1[i] = W1[i]; sW2[i] = W2[i]; }
    if (t < 16) {
        sb1[t] = b1[t]; sb2[t] = b2[t]; sc[t] = ew[t]; se[t] = ebv[t];
        // BN affine from previous layer stats (computed per block, no separate kernel)
        double s = g_stats5[(layer - 1) * 32 + t], q = g_stats5[(layer - 1) * 32 + 16 + t];
        float mu  = (float)(s / (double)NN);
        float var = (float)(q / (double)NN) - mu * mu;
        float a   = gamma[t] * rsqrtf(fmaxf(var, 0.f) + 1e-5f);
        sa[t] = a; sbb[t] = beta[t] - mu * a;
        ssum[t] = 0.f; ssq[t] = 0.f;
    }
    __syncthreads();
    float ope = 1.f + epsp[0];
    int lane  = t & 31;
    int l16   = lane & 15;
    int hw    = lane >> 4;            // node half within warp
    int hwb   = lane & 16;            // base lane of my half
    int eslot = l16 >> 2, q = l16 & 3;
    float a0 = sa[q*4+0], a1 = sa[q*4+1], a2 = sa[q*4+2], a3 = sa[q*4+3];
    float p0 = sbb[q*4+0], p1 = sbb[q*4+1], p2 = sbb[q*4+2], p3 = sbb[q*4+3];
    float c0 = sc[q*4+0], c1 = sc[q*4+1], c2 = sc[q*4+2], c3 = sc[q*4+3];
    float e0 = se[q*4+0], e1 = se[q*4+1], e2 = se[q*4+2], e3 = se[q*4+3];
    int gw = blockIdx.x * 8 + (t >> 5);
    int np = gridDim.x * 8;           // warps = pairs per sweep
    float lsum = 0.f, lsq = 0.f;
    for (int p = gw; p < NN / 2; p += np) {
        int n = p * 2 + hw;
        int beg = g_off[n], end = g_off[n + 1];
        float ax = 0.f, ay = 0.f, az = 0.f, aw = 0.f;
        int j = beg + eslot;
        int2 swc = (j < end) ? __ldg(&g_csr[j]) : make_int2(0, 0);
        while (__any_sync(FULL, j < end)) {
            bool act = j < end;
            int jn = j + 4;
            int2 swn = (jn < end) ? __ldg(&g_csr[jn]) : make_int2(0, 0);
            if (act) {
                int   src = swc.x;
                float wv  = __int_as_float(swc.y);
                float4 xv = __ldg(&xin4[src * 4 + q]);
                ax += fmaxf(fmaf(a0, xv.x, p0) + fmaf(wv, c0, e0), 0.f);
                ay += fmaxf(fmaf(a1, xv.y, p1) + fmaf(wv, c1, e1), 0.f);
                az += fmaxf(fmaf(a2, xv.z, p2) + fmaf(wv, c2, e2), 0.f);
                aw += fmaxf(fmaf(a3, xv.w, p3) + fmaf(wv, c3, e3), 0.f);
            }
            swc = swn; j = jn;
        }
        // reduce 4 edge slots within each half (offsets 4, 8 stay inside the half)
        #pragma unroll
        for (int ofs = 4; ofs < 16; ofs <<= 1) {
            ax += __shfl_xor_sync(FULL, ax, ofs); ay += __shfl_xor_sync(FULL, ay, ofs);
            az += __shfl_xor_sync(FULL, az, ofs); aw += __shfl_xor_sync(FULL, aw, ofs);
        }
        // redistribute: lane l16 gets dim l16 of its half's aggregate
        int srcl = hwb + (l16 >> 2);
        float vx = __shfl_sync(FULL, ax, srcl);
        float vy = __shfl_sync(FULL, ay, srcl);
        float vz = __shfl_sync(FULL, az, srcl);
        float vw = __shfl_sync(FULL, aw, srcl);
        float lo = (l16 & 1) ? vy : vx;
        float hi = (l16 & 1) ? vw : vz;
        float aggv = (l16 & 2) ? hi : lo;
        float xn = fmaf(sa[l16], xin[n * DIM + l16], sbb[l16]);
        float h  = ope * xn + aggv;
        float tj = sb1[l16];
        #pragma unroll
        for (int dd = 0; dd < 16; dd++) {
            float hd = __shfl_sync(FULL, h, hwb + dd);
            tj = fmaf(hd, sW1[dd * 16 + l16], tj);
        }
        tj = fmaxf(tj, 0.f);
        float oj = sb2[l16];
        #pragma unroll
        for (int dd = 0; dd < 16; dd++) {
            float td = __shfl_sync(FULL, tj, hwb + dd);
            oj = fmaf(td, sW2[dd * 16 + l16], oj);
        }
        float y = fmaxf(oj, 0.f);
        xout[n * DIM + l16] = y;
        lsum += y; lsq += y * y;
    }
    atomicAdd(&ssum[l16], lsum); atomicAdd(&ssq[l16], lsq);
    __syncthreads();
    if (t < 16) {
        atomicAdd(&g_stats5[layer * 32 + t],      (double)ssum[t]);
        atomicAdd(&g_stats5[layer * 32 + 16 + t], (double)ssq[t]);
    }
}

// ---------------- global mean pool (applies final BN affine inline) ----------------
__global__ void k_pool(const int* __restrict__ batch,
                       const float* __restrict__ gamma, const float* __restrict__ beta) {
    __shared__ float sp[BGR * DIM];
    __shared__ float sa[16], sbb[16];
    int t = threadIdx.x;
    for (int i = t; i < BGR * DIM; i += 256) sp[i] = 0.f;
    if (t < 16) {
        double s = g_stats5[4 * 32 + t], q = g_stats5[4 * 32 + 16 + t];
        float mu  = (float)(s / (double)NN);
        float var = (float)(q / (double)NN) - mu * mu;
        float a   = gamma[t] * rsqrtf(fmaxf(var, 0.f) + 1e-5f);
        sa[t] = a; sbb[t] = beta[t] - mu * a;
    }
    __syncthreads();
    int st = gridDim.x * 256;
    const float* xb = (const float*)g_xb0;
    for (int idx = blockIdx.x * 256 + t; idx < NN * DIM; idx += st) {
        int n = idx >> 4, dd = idx & 15;
        int bt = batch[n];
        float v = fmaf(sa[dd], xb[idx], sbb[dd]);
        atomicAdd(&sp[bt * DIM + dd], v);
    }
    __syncthreads();
    for (int i = t; i < BGR * DIM; i += 256) atomicAdd(&g_pool[i], sp[i]);
}

__device__ __forceinline__ int lbound(const int* a, int n, int key) {
    int lo = 0, hi = n;
    while (lo < hi) { int mid = (lo + hi) >> 1; if (a[mid] < key) lo = mid + 1; else hi = mid; }
    return lo;
}

__global__ void k_head(const int* __restrict__ batch,
                       const float* __restrict__ fw, const float* __restrict__ fb,
                       float* __restrict__ out) {
    __shared__ float sm[16];
    __shared__ int scnt;
    int b = blockIdx.x, t = threadIdx.x;
    if (t == 0) {
        int lo = lbound(batch, NN, b);
        int hi = lbound(batch, NN, b + 1);
        scnt = max(hi - lo, 1);
    }
    __syncthreads();
    if (t < 16) sm[t] = g_pool[b * DIM + t] / (float)scnt;
    __syncthreads();
    float acc = fb[t];
    #pragma unroll
    for (int dd = 0; dd < 16; dd++) acc += sm[dd] * fw[dd * EMBD + t];
    out[BGR * EMBD + b * EMBD + t] = fmaxf(acc, 0.f);
}

// ---------------- RNA: bucket build, fused G+L (list stores c*8) ----------------
__global__ void k_bucket2(const int* __restrict__ tokG, const int* __restrict__ tokL) {
    __shared__ int cnt[TMAX + 1];
    __shared__ int offs[TMAX + 1];
    int isL = blockIdx.x >> 6;
    int b   = blockIdx.x & 63;
    int L = isL ? LL : LG;
    int T = isL ? TMAX : 5;
    const int* tok  = isL ? tokL : tokG;
    int* list = isL ? g_blistL : g_blistG;
    int* boff = isL ? g_boffL  : g_boffG;
    int t = threadIdx.x;
    if (t <= T) cnt[t] = 0;
    __syncthreads();
    const int* tb = tok + b * L;
    for (int c = t; c < L; c += 256) atomicAdd(&cnt[tb[c]], 1);
    __syncthreads();
    if (t == 0) {
        int acc = 0;
        for (int i = 0; i < T; i++) { offs[i] = acc; acc += cnt[i]; }
        offs[T] = acc;
    }
    __syncthreads();
    if (t <= T) boff[b * (TMAX + 1) + t] = offs[t];
    if (t < T) cnt[t] = offs[t];   // cursors
    __syncthreads();
    for (int c = t; c < L; c += 256) {
        int pos = atomicAdd(&cnt[tb[c]], 1);
        list[b * L + pos] = c << 3;   // pre-multiplied by 8
    }
}

// ---------------- RNA: W~ gather-sum, fused G+L ----------------
__global__ void k_wtilde4(const float* __restrict__ wG, const float* __restrict__ wL) {
    __shared__ int soff[TMAX + 1];
    int isL = blockIdx.x < 2048 ? 1 : 0;
    int bf  = isL ? blockIdx.x : (blockIdx.x - 2048);
    int b = bf >> 5, f = bf & 31;
    int L = isL ? LL : LG;
    int T = isL ? TMAX : 5;
    const float* w    = isL ? wL : wG;
    const int*   list = isL ? g_blistL : g_blistG;
    const int*   boff = isL ? g_boffL  : g_boffG;
    float*       wt   = isL ? g_wtL    : g_wtG;
    int tid = threadIdx.x;
    if (tid <= T) soff[tid] = boff[b * (TMAX + 1) + tid];
    __syncthreads();
    const int*   lst = list + b * L;
    const float* wf  = w + (size_t)f * L * 8;
    float* o = wt + (size_t)bf * (T * 8);
    int wid = tid >> 5, lane = tid & 31;
    int pg = lane >> 3, k = lane & 7;
    for (int tt = wid; tt < T; tt += 8) {
        int lo = soff[tt], hi = soff[tt + 1];
        float acc = 0.f;
        for (int p = lo + pg; p < hi; p += 4) {
            int c8 = __ldg(&lst[p]);
            acc += __ldg(&wf[c8 + k]);
        }
        acc += __shfl_xor_sync(FULL, acc, 8);
        acc += __shfl_xor_sync(FULL, acc, 16);
        if (lane < 8) o[tt * 8 + k] = acc;
    }
}

// ---------------- RNA: conv-y, fused G+L ----------------
__global__ void k_convy2(const float* __restrict__ embG, const float* __restrict__ embL,
                         const float* __restrict__ cbG, const float* __restrict__ cbL) {
    __shared__ float swt[TMAX * 8];
    int isL = blockIdx.x < 2048 ? 1 : 0;
    int bf  = isL ? blockIdx.x : (blockIdx.x - 2048);
    int b = bf >> 5, f = bf & 31;
    int T = isL ? TMAX : 5;
    const float* emb = isL ? embL : embG;
    const float* cb  = isL ? cbL  : cbG;
    const float* wt  = isL ? g_wtL : g_wtG;
    float*       y   = isL ? g_yL  : g_yG;
    int t = threadIdx.x;
    const float* src = wt + (size_t)bf * (T * 8);
    for (int i = t; i < T * 8; i += 128) swt[i] = src[i];
    __syncthreads();
    if (t < 121) {
        float acc0 = cb[f], acc1 = 0.f;
        for (int tt = 0; tt < T; tt++) {
            const float* er = emb + tt * EMBD;
            acc0 = fmaf(swt[tt*8+0], er[t+0], acc0);
            acc1 = fmaf(swt[tt*8+1], er[t+1], acc1);
            acc0 = fmaf(swt[tt*8+2], er[t+2], acc0);
            acc1 = fmaf(swt[tt*8+3], er[t+3], acc1);
            acc0 = fmaf(swt[tt*8+4], er[t+4], acc0);
            acc1 = fmaf(swt[tt*8+5], er[t+5], acc1);
            acc0 = fmaf(swt[tt*8+6], er[t+6], acc0);
            acc1 = fmaf(swt[tt*8+7], er[t+7], acc1);
        }
        y[b * FCIN + f * 121 + t] = acc0 + acc1;
    }
}

// ---------------- RNA: fc on 0.5*(yG+yL) ----------------
__global__ void k_fc(const float* __restrict__ fw, const float* __restrict__ fb,
                     float* __restrict__ out) {
    __shared__ float sy[FCIN];
    __shared__ float sred[4][EMBD];
    int b = blockIdx.x, tid = threadIdx.x;
    for (int i = tid; i < FCIN; i += 512)
        sy[i] = 0.5f * (g_yG[b * FCIN + i] + g_yL[b * FCIN + i]);
    __syncthreads();
    int t = tid & 127, chunk = tid >> 7;
    int lo = chunk * (FCIN / 4), hi = lo + (FCIN / 4);
    float a0 = 0.f, a1 = 0.f;
    for (int i = lo; i < hi; i += 2) {
        a0 = fmaf(sy[i + 0], __ldg(&fw[(i + 0) * EMBD + t]), a0);
        a1 = fmaf(sy[i + 1], __ldg(&fw[(i + 1) * EMBD + t]), a1);
    }
    sred[chunk][t] = a0 + a1;
    __syncthreads();
    if (tid < 128)
        out[b * EMBD + tid] = fb[tid] +
            ((sred[0][tid] + sred[1][tid]) + (sred[2][tid] + sred[3][tid]));
}

// ---------------- launch ----------------
extern "C" void kernel_launch(void* const* d_in, const int* in_sizes, int n_in,
                              void* d_out, int out_size) {
    const float* px   = (const float*)d_in[0];
    const int*   ei   = (const int*)d_in[1];
    const float* pw   = (const float*)d_in[2];
    const int*   pbat = (const int*)d_in[3];
    const int*   rg   = (const int*)d_in[4];
    const int*   rl   = (const int*)d_in[5];
    const float* g1w1 = (const float*)d_in[6];
    const float* g1b1 = (const float*)d_in[7];
    const float* g1w2 = (const float*)d_in[8];
    const float* g1b2 = (const float*)d_in[9];
    const float* g1ew = (const float*)d_in[10];
    const float* g1eb = (const float*)d_in[11];
    const float* g1ep = (const float*)d_in[12];
    const float* gw1  = (const float*)d_in[13];
    const float* gb1  = (const float*)d_in[14];
    const float* gw2  = (const float*)d_in[15];
    const float* gb2  = (const float*)d_in[16];
    const float* gew  = (const float*)d_in[17];
    const float* geb  = (const float*)d_in[18];
    const float* gep  = (const float*)d_in[19];
    const float* bng  = (const float*)d_in[20];
    const float* bnb  = (const float*)d_in[21];
    const float* fxpw = (const float*)d_in[22];
    const float* fxpb = (const float*)d_in[23];
    const float* emb1 = (const float*)d_in[24];
    const float* emb2 = (const float*)d_in[25];
    const float* c1w  = (const float*)d_in[26];
    const float* c1b  = (const float*)d_in[27];
    const float* c2w  = (const float*)d_in[28];
    const float* c2b  = (const float*)d_in[29];
    const float* fxw  = (const float*)d_in[30];
    const float* fxb  = (const float*)d_in[31];
    float* out = (float*)d_out;

    const int NB_SCAN = (NN + 1 + 1023) / 1024;  // 98

    // Fork: RNA branch on a side stream, concurrent with the protein chain.
    cudaStream_t s1;
    cudaStreamCreateWithFlags(&s1, cudaStreamNonBlocking);
    cudaEvent_t eF, eJ;
    cudaEventCreateWithFlags(&eF, cudaEventDisableTiming);
    cudaEventCreateWithFlags(&eJ, cudaEventDisableTiming);
    cudaEventRecord(eF, 0);
    cudaStreamWaitEvent(s1, eF, 0);

    k_bucket2<<<128, 256, 0, s1>>>(rg, rl);
    k_wtilde4<<<4096, 256, 0, s1>>>(c1w, c2w);
    k_convy2<<<4096, 128, 0, s1>>>(emb1, emb2, c1b, c2b);
    k_fc<<<BGR, 512, 0, s1>>>(fxw, fxb, out);
    cudaEventRecord(eJ, s1);

    // Protein chain on the main (capture) stream
    k_initA<<<128, 256>>>();
    k_padhist<<<1024, 256>>>(px, ei);
    k_scan1<<<NB_SCAN, 1024>>>();
    k_scan3b<<<NB_SCAN, 1024>>>();
    k_scatter<<<1024, 256>>>(ei, pw);
    k_gine33<<<1184, 256>>>(g1w1, g1b1, g1w2, g1b2, g1ew, g1eb, g1ep);
    for (int i = 0; i < 4; i++) {
        k_gine16<<<1184, 256>>>(gw1 + i * 256, gb1 + i * 16,
                                gw2 + i * 256, gb2 + i * 16,
                                gew + i * 16,  geb + i * 16,
                                gep + i, bng + i * 16, bnb + i * 16,
                                i + 1, i & 1);
    }
    k_pool<<<296, 256>>>(pbat, bng + 4 * 16, bnb + 4 * 16);
    k_head<<<BGR, 128>>>(pbat, fxpw, fxpb, out);

    // Join RNA branch back into the capture stream
    cudaStreamWaitEvent(0, eJ, 0);

    cudaStreamDestroy(s1);
    cudaEventDestroy(eF);
    cudaEventDestroy(eJ);
}